// round 15
// baseline (speedup 1.0000x reference)
#include <cuda_runtime.h>
#include <cuda_fp16.h>
#include <math.h>
#include <stdint.h>

#define BSZ 4
#define NX 8192
#define NY 1024
#define KNN 20
#define CD 24
#define HD 128
#define NB 5
#define NROWS (BSZ*NX*KNN)   /* 655360 */
#define NPTS  (BSZ*NX)       /* 32768  */
#define BN_EPS 1e-5f

typedef unsigned long long ull;

/* ---------------- f32x2 packed helpers ---------------- */
__device__ __forceinline__ ull ffma2(ull a, ull b, ull c) {
    ull d;
    asm("fma.rn.f32x2 %0, %1, %2, %3;" : "=l"(d) : "l"(a), "l"(b), "l"(c));
    return d;
}
__device__ __forceinline__ ull pack2(float lo, float hi) {
    ull d;
    asm("mov.b64 %0, {%1, %2};" : "=l"(d) : "f"(lo), "f"(hi));
    return d;
}
__device__ __forceinline__ float2 unpack2(ull v) {
    float2 r;
    asm("mov.b64 {%0, %1}, %2;" : "=f"(r.x), "=f"(r.y) : "l"(v));
    return r;
}

/* ---------------- warp mma m16n8k16 f16 -> f32 ---------------- */
__device__ __forceinline__ void mma16816(float* d, uint32_t a0, uint32_t a1,
                                         uint32_t a2, uint32_t a3,
                                         uint32_t b0, uint32_t b1) {
    asm volatile(
        "mma.sync.aligned.m16n8k16.row.col.f32.f16.f16.f32 "
        "{%0,%1,%2,%3}, {%4,%5,%6,%7}, {%8,%9}, {%0,%1,%2,%3};"
        : "+f"(d[0]), "+f"(d[1]), "+f"(d[2]), "+f"(d[3])
        : "r"(a0), "r"(a1), "r"(a2), "r"(a3), "r"(b0), "r"(b1));
}

/* ---------------- scratch ---------------- */
__device__ int    g_idx[NROWS];                 /* 2.6 MB */
__device__ float  g_U[BSZ*NY*HD];               /* 2 MB   */
__device__ float  g_V[BSZ*NX*HD];               /* 16 MB  */
__device__ __half g_h2h[(size_t)NROWS*HD];      /* 168 MB */
__device__ float  g_pmax[NPTS*CD];              /* 3 MB   */
__device__ float  g_pmin[NPTS*CD];              /* 3 MB   */
__device__ __half g_W16[HD*HD];                 /* w2^T fp16 */
__device__ float  g_sum[3*HD];
__device__ float  g_sumsq[3*HD];
__device__ float  g_scale[3*HD];
__device__ float  g_shift[3*HD];
__device__ int    g_cnt[3];

__device__ __forceinline__ void bn_finalize(int L, int C, float invN,
                                            const float* g, const float* b, int c) {
    if (c < C) {
        float mean = g_sum[L*HD + c] * invN;
        float var  = g_sumsq[L*HD + c] * invN - mean*mean;
        float sc = g[c] * rsqrtf(var + BN_EPS);
        g_scale[L*HD + c] = sc;
        g_shift[L*HD + c] = b[c] - mean*sc;
    }
}

/* ---------------- K1: fused KNN + preU + preV + prepW ----------------------
   blocks [0,128): knn (b = blk>>5, tile = blk&31; block 0 zeros stats).
   blocks [128,256): U (32 rows each). [256,768): V (64 rows each).
   blocks [768,832): w2^T -> fp16 (256 elems each).  256 threads everywhere. */
__global__ void __launch_bounds__(256) k_pre(const float* __restrict__ p,
                                             const float* __restrict__ pc,
                                             const float* __restrict__ feat,
                                             const float* __restrict__ w1,
                                             const float* __restrict__ w2) {
    __shared__ float qx[NY], qy[NY], qz[NY], qn[NY];   /* knn use */
    __shared__ float in_s[32][28];                     /* U use   */
    __shared__ float ps[64][4];                        /* V use   */
    int t = threadIdx.x, blk = blockIdx.x;

    if (blk < 128) {
        int b = blk >> 5;
        if (blk == 0) {
            for (int c = t; c < 3*HD; c += 256) { g_sum[c] = 0.f; g_sumsq[c] = 0.f; }
            if (t < 3) g_cnt[t] = 0;
        }
        for (int j = t; j < NY; j += 256) {
            float x = pc[(b*NY + j)*3 + 0];
            float y = pc[(b*NY + j)*3 + 1];
            float z = pc[(b*NY + j)*3 + 2];
            qx[j] = x; qy[j] = y; qz[j] = z;
            qn[j] = x*x + y*y + z*z;
        }
        __syncthreads();

        int n = (blk & 31) * 256 + t;
        float px = p[(b*NX + n)*3 + 0];
        float py = p[(b*NX + n)*3 + 1];
        float pz = p[(b*NX + n)*3 + 2];
        float pn = px*px + py*py + pz*pz;

        float bd[KNN]; int bi[KNN];
#pragma unroll
        for (int s = 0; s < KNN; s++) { bd[s] = 3.4e38f; bi[s] = 0; }
        float worst = 3.4e38f; int wpos = 0;

        for (int j = 0; j < NY; j++) {
            float d = pn + qn[j] - 2.f*(px*qx[j] + py*qy[j] + pz*qz[j]);
            if (d < worst) {
#pragma unroll
                for (int s = 0; s < KNN; s++) if (s == wpos) { bd[s] = d; bi[s] = j; }
                worst = bd[0]; wpos = 0;
#pragma unroll
                for (int s = 1; s < KNN; s++) if (bd[s] > worst) { worst = bd[s]; wpos = s; }
            }
        }
        int base = (b*NX + n)*KNN;
#pragma unroll
        for (int s = 0; s < KNN; s++) g_idx[base + s] = bi[s];
    } else if (blk < 256) {
        int base = (blk - 128) * 32;
        for (int e = t; e < 32*27; e += 256) {
            int r = e / 27, k = e % 27;
            int row = base + r;
            in_s[r][k] = (k < 3) ? pc[row*3 + k] : feat[row*24 + (k - 3)];
        }
        __syncthreads();
        if (t < 128) {
            float wr[27];
#pragma unroll
            for (int d = 0; d < 3; d++)  wr[d]     = w1[d*HD + t];
#pragma unroll
            for (int k = 0; k < 24; k++) wr[3 + k] = w1[(6 + k)*HD + t];
            for (int r = 0; r < 32; r++) {
                float acc = 0.f;
#pragma unroll
                for (int k = 0; k < 27; k++) acc = fmaf(in_s[r][k], wr[k], acc);
                g_U[(base + r)*HD + t] = acc;
            }
        }
    } else if (blk < 768) {
        int base = (blk - 256) * 64;
        for (int e = t; e < 64*3; e += 256) {
            int r = e / 3, d = e % 3;
            ps[r][d] = p[(base + r)*3 + d];
        }
        __syncthreads();
        if (t < 128) {
            float wd0 = w1[3*HD + t] - w1[0*HD + t];
            float wd1 = w1[4*HD + t] - w1[1*HD + t];
            float wd2 = w1[5*HD + t] - w1[2*HD + t];
            for (int r = 0; r < 64; r++) {
                float v = fmaf(ps[r][0], wd0, fmaf(ps[r][1], wd1, ps[r][2]*wd2));
                g_V[(base + r)*HD + t] = v;
            }
        }
    } else {
        int e = (blk - 768) * 256 + t;   /* [0,16384) */
        int n = e >> 7, k = e & 127;
        g_W16[e] = __float2half(w2[k*HD + n]);
    }
}

/* ---------------- K2: stats of h1 + fused finalize layer 0 ---------------- */
__global__ void k_stats1(const float* __restrict__ bn1g, const float* __restrict__ bn1b,
                         float invN) {
    __shared__ int uo[512], vo[512];
    __shared__ int lastflag;
    int blk = blockIdx.x, t = threadIdx.x;
    int base = blk * 512;
    for (int r = t; r < 512; r += 256) {
        int grow = base + r;
        int j = g_idx[grow];
        int b = grow / (NX*KNN);
        int n = (grow / KNN) % NX;
        uo[r] = (b*NY + j)*HD;
        vo[r] = (b*NX + n)*HD;
    }
    __syncthreads();
    int c = t & 127, rg = t >> 7;
    float s = 0.f, s2 = 0.f;
    for (int r = rg; r < 512; r += 2) {
        float v = g_U[uo[r] + c] + g_V[vo[r] + c];
        s += v; s2 += v*v;
    }
    atomicAdd(&g_sum[c], s);
    atomicAdd(&g_sumsq[c], s2);
    __threadfence();
    __syncthreads();
    if (t == 0) lastflag = (atomicAdd(&g_cnt[0], 1) == (int)gridDim.x - 1);
    __syncthreads();
    if (lastflag) bn_finalize(0, 128, invN, bn1g, bn1b, t);
}

/* ---------------- K3: conv2 via warp mma (verified) ---------------- */
#define C2_PH 136
#define C2_PW 68
#define C2_AS 2048
#define C2_BS (2048 + 34816)
#define C2_SMEM (2048 + 2*34816)
__global__ void __launch_bounds__(256) k_conv2(const float* __restrict__ bn2g,
                                               const float* __restrict__ bn2b,
                                               float invN) {
    extern __shared__ char smemraw[];
    float* sc = (float*)smemraw;
    float* sh = sc + 128;
    int*   uo = (int*)(sh + 128);
    int*   vo = uo + 128;
    __shared__ int lastflag;

    int t = threadIdx.x, blk = blockIdx.x;
    int lane = t & 31, wid = t >> 5;
    int rbase = blk * 128;
    __half* As = (__half*)(smemraw + C2_AS);
    __half* Bs = (__half*)(smemraw + C2_BS);

    if (t < 128) {
        int grow = rbase + t;
        int j = g_idx[grow];
        int b = grow / (NX*KNN);
        int n = (grow / KNN) % NX;
        uo[t] = (b*NY + j)*HD;
        vo[t] = (b*NX + n)*HD;
    } else {
        int c = t - 128;
        sc[c] = g_scale[c];
        sh[c] = g_shift[c];
    }
    __syncthreads();

    for (int e = t; e < HD*HD; e += 256) {
        int n = e >> 7, k = e & 127;
        Bs[n*C2_PH + k] = g_W16[e];
    }
    {
        int k = t & 127;
        for (int r = (t >> 7); r < 128; r += 2) {
            float v = g_U[uo[r] + k] + g_V[vo[r] + k];
            v = fmaf(sc[k], v, sh[k]);
            v = (v > 0.f) ? v : 0.2f*v;
            As[r*C2_PH + k] = __float2half(v);
        }
    }
    __syncthreads();

    const uint32_t* As32 = (const uint32_t*)As;
    const uint32_t* Bs32 = (const uint32_t*)Bs;
    int gid = lane >> 2, tid = lane & 3;
    int ar0 = wid*16 + gid;
    float d[16][4];
#pragma unroll
    for (int nb = 0; nb < 16; nb++)
#pragma unroll
        for (int j = 0; j < 4; j++) d[nb][j] = 0.f;

#pragma unroll
    for (int k0 = 0; k0 < 8; k0++) {
        int kc = k0*8 + tid;
        uint32_t a0 = As32[ar0*C2_PW + kc];
        uint32_t a1 = As32[(ar0+8)*C2_PW + kc];
        uint32_t a2 = As32[ar0*C2_PW + kc + 4];
        uint32_t a3 = As32[(ar0+8)*C2_PW + kc + 4];
#pragma unroll
        for (int nb = 0; nb < 16; nb++) {
            uint32_t b0 = Bs32[(nb*8+gid)*C2_PW + kc];
            uint32_t b1 = Bs32[(nb*8+gid)*C2_PW + kc + 4];
            mma16816(d[nb], a0, a1, a2, a3, b0, b1);
        }
    }
    __syncthreads();

    __half2* hst2 = (__half2*)(smemraw + C2_AS);
#pragma unroll
    for (int nb = 0; nb < 16; nb++) {
        hst2[ar0*C2_PW + nb*4 + tid]     = __floats2half2_rn(d[nb][0], d[nb][1]);
        hst2[(ar0+8)*C2_PW + nb*4 + tid] = __floats2half2_rn(d[nb][2], d[nb][3]);
    }
    __syncthreads();
    {
        __half2* dst = (__half2*)&g_h2h[(size_t)rbase*HD];
        for (int e = t; e < 128*64; e += 256) {
            int r = e >> 6, j = e & 63;
            dst[e] = hst2[r*C2_PW + j];
        }
    }
    {
        int c2 = t & 63, rg = t >> 6;
        float s0 = 0.f, q0 = 0.f, s1 = 0.f, q1 = 0.f;
        for (int r = rg*32; r < rg*32 + 32; r++) {
            float2 f = __half22float2(hst2[r*C2_PW + c2]);
            s0 += f.x; q0 += f.x*f.x;
            s1 += f.y; q1 += f.y*f.y;
        }
        atomicAdd(&g_sum[HD + 2*c2],     s0);
        atomicAdd(&g_sumsq[HD + 2*c2],   q0);
        atomicAdd(&g_sum[HD + 2*c2+1],   s1);
        atomicAdd(&g_sumsq[HD + 2*c2+1], q1);
    }
    __threadfence();
    __syncthreads();
    if (t == 0) lastflag = (atomicAdd(&g_cnt[1], 1) == (int)gridDim.x - 1);
    __syncthreads();
    if (lastflag) bn_finalize(1, 128, invN, bn2g, bn2b, t);
}

/* ---------------- K4: conv3 via warp mma (verified R14) + pool -------------- */
#define C3_AS 0
#define C3_WH 41600
#define C3_WL (41600 + 6272)
#define C3_H3 (41600 + 2*6272)
#define C3_SC (C3_H3 + 16000)
#define C3_SH (C3_SC + 512)
#define C3_RED (C3_SH + 512)
#define SMEM3 (C3_RED + 256)
__global__ void __launch_bounds__(192) k_conv3p(const float* __restrict__ w3,
                                                const float* __restrict__ bn3g,
                                                const float* __restrict__ bn3b,
                                                float invN) {
    extern __shared__ char smemraw[];
    __half* Wh = (__half*)(smemraw + C3_WH);
    __half* Wl = (__half*)(smemraw + C3_WL);
    float*  h3s = (float*)(smemraw + C3_H3);
    float*  sc = (float*)(smemraw + C3_SC);
    float*  sh = (float*)(smemraw + C3_SH);
    float*  red = (float*)(smemraw + C3_RED);
    __shared__ int lastflag;

    int t = threadIdx.x, blk = blockIdx.x;
    int lane = t & 31, w = t >> 5;
    int rbase = blk * 160;

    for (int e = t; e < 24*128; e += 192) {
        int n = e % 24, k = e / 24;
        float vv = w3[e];
        __half hi = __float2half(vv);
        Wh[n*130 + k] = hi;
        Wl[n*130 + k] = __float2half(vv - __half2float(hi));
    }
    if (t < 128) { sc[t] = g_scale[HD + t]; sh[t] = g_shift[HD + t]; }
    if (t < 48)  red[t] = 0.f;
    __syncthreads();
    /* stage A: h2 fp16 -> bn2+lrelu -> fp16 */
    {
        __half2* As2 = (__half2*)(smemraw + C3_AS);
        const __half2* hp = (const __half2*)g_h2h + (size_t)rbase*64;
        for (int e = t; e < 160*64; e += 192) {
            int r = e >> 6, kp = e & 63;
            float2 f = __half22float2(hp[(size_t)r*64 + kp]);
            int k0 = 2*kp;
            float v0 = fmaf(sc[k0],   f.x, sh[k0]);   v0 = (v0 > 0.f) ? v0 : 0.2f*v0;
            float v1 = fmaf(sc[k0+1], f.y, sh[k0+1]); v1 = (v1 > 0.f) ? v1 : 0.2f*v1;
            As2[r*65 + kp] = __floats2half2_rn(v0, v1);
        }
    }
    __syncthreads();

    const uint32_t* A32 = (const uint32_t*)(smemraw + C3_AS);
    const uint32_t* W32h = (const uint32_t*)(smemraw + C3_WH);
    const uint32_t* W32l = (const uint32_t*)(smemraw + C3_WL);
    int gid = lane >> 2, tid = lane & 3;
    int nb = w >> 1, mtb = (w & 1)*5;
    float d[5][4];
#pragma unroll
    for (int m = 0; m < 5; m++)
#pragma unroll
        for (int j = 0; j < 4; j++) d[m][j] = 0.f;

#pragma unroll
    for (int k0 = 0; k0 < 8; k0++) {
        int kc = k0*8 + tid;
        uint32_t bh0 = W32h[(nb*8+gid)*65 + kc];
        uint32_t bh1 = W32h[(nb*8+gid)*65 + kc + 4];
        uint32_t bl0 = W32l[(nb*8+gid)*65 + kc];
        uint32_t bl1 = W32l[(nb*8+gid)*65 + kc + 4];
#pragma unroll
        for (int m = 0; m < 5; m++) {
            int row = (mtb + m)*16 + gid;
            uint32_t a0 = A32[row*65 + kc];
            uint32_t a1 = A32[(row+8)*65 + kc];
            uint32_t a2 = A32[row*65 + kc + 4];
            uint32_t a3 = A32[(row+8)*65 + kc + 4];
            mma16816(d[m], a0, a1, a2, a3, bh0, bh1);
            mma16816(d[m], a0, a1, a2, a3, bl0, bl1);
        }
    }

    {
        int col = nb*8 + tid*2;
        float se = 0.f, qe = 0.f, so = 0.f, qo = 0.f;
#pragma unroll
        for (int m = 0; m < 5; m++) {
            int row = (mtb + m)*16 + gid;
            h3s[row*25 + col]       = d[m][0];
            h3s[row*25 + col+1]     = d[m][1];
            h3s[(row+8)*25 + col]   = d[m][2];
            h3s[(row+8)*25 + col+1] = d[m][3];
            se += d[m][0] + d[m][2]; qe += d[m][0]*d[m][0] + d[m][2]*d[m][2];
            so += d[m][1] + d[m][3]; qo += d[m][1]*d[m][1] + d[m][3]*d[m][3];
        }
        atomicAdd(&red[col], se);
        atomicAdd(&red[24 + col], qe);
        atomicAdd(&red[col+1], so);
        atomicAdd(&red[24 + col+1], qo);
    }
    __syncthreads();

    {
        int pl = t / 24, c2 = t % 24;
        float mx = -3.4e38f, mn = 3.4e38f;
#pragma unroll
        for (int kk = 0; kk < KNN; kk++) {
            float v = h3s[(pl*KNN + kk)*25 + c2];
            mx = fmaxf(mx, v); mn = fminf(mn, v);
        }
        int pt = blk*8 + pl;
        g_pmax[pt*24 + c2] = mx;
        g_pmin[pt*24 + c2] = mn;
    }
    if (t < 24) {
        atomicAdd(&g_sum[2*HD + t],   red[t]);
        atomicAdd(&g_sumsq[2*HD + t], red[24 + t]);
    }
    __threadfence();
    __syncthreads();
    if (t == 0) lastflag = (atomicAdd(&g_cnt[2], 1) == (int)gridDim.x - 1);
    __syncthreads();
    if (lastflag) bn_finalize(2, 24, invN, bn3g, bn3b, t);
}

/* ---------------- K5: ResNet-FC head: mma 3-term split (verified R14) ------- */
#define H_NET 0
#define H_AH  32768
#define H_AL  49408
#define H_WH  66048
#define H_WL  99328
#define H_CB  132608
#define H_PB  138752
#define H_FO  139520
#define SMEMH 140288
__global__ void __launch_bounds__(256) k_head(const float* __restrict__ p,
                       const float* __restrict__ fpw, const float* __restrict__ fpb,
                       const float* __restrict__ fcw, const float* __restrict__ fcb,
                       const float* __restrict__ b0w, const float* __restrict__ b0b,
                       const float* __restrict__ b1w, const float* __restrict__ b1b,
                       const float* __restrict__ fow, const float* __restrict__ fob,
                       float* __restrict__ out) {
    extern __shared__ char sm[];
    float*   net = (float*)(sm + H_NET);
    __half2* Ah2 = (__half2*)(sm + H_AH);
    __half2* Al2 = (__half2*)(sm + H_AL);
    __half*  WhH = (__half*)(sm + H_WH);
    __half*  WlH = (__half*)(sm + H_WL);
    float*   cb  = (float*)(sm + H_CB);
    float*   pb  = (float*)(sm + H_PB);
    float*   fo  = (float*)(sm + H_FO);

    int t = threadIdx.x, lane = t & 31, w = t >> 5;
    int gid = lane >> 2, tid = lane & 3;
    int mt = w & 3, nh = w >> 2;
    int row = mt*16 + gid;
    int base = blockIdx.x * 64;

    for (int e = t; e < 64*CD; e += 256) {
        int c2 = e % 24;
        float scv = g_scale[2*HD + c2], shv = g_shift[2*HD + c2];
        float v = (scv >= 0.f) ? g_pmax[base*24 + e] : g_pmin[base*24 + e];
        v = fmaf(scv, v, shv);
        cb[e] = (v > 0.f) ? v : 0.2f*v;
    }
    if (t < 192) pb[t] = p[base*3 + t];
    if (t < 128) fo[t] = fow[t];
    __syncthreads();

    int cg  = (t & 31) * 4;
    int row0 = (t >> 5) * 8;

    { /* net = p @ fc_p_w + b */
        float4 w0 = *(const float4*)&fpw[0*HD + cg];
        float4 w1 = *(const float4*)&fpw[1*HD + cg];
        float4 w2 = *(const float4*)&fpw[2*HD + cg];
        float4 b4 = *(const float4*)&fpb[cg];
#pragma unroll
        for (int rr = 0; rr < 8; rr++) {
            int rw = row0 + rr;
            float p0 = pb[rw*3+0], p1 = pb[rw*3+1], p2 = pb[rw*3+2];
            float4 v;
            v.x = fmaf(p0,w0.x, fmaf(p1,w1.x, fmaf(p2,w2.x, b4.x)));
            v.y = fmaf(p0,w0.y, fmaf(p1,w1.y, fmaf(p2,w2.y, b4.y)));
            v.z = fmaf(p0,w0.z, fmaf(p1,w1.z, fmaf(p2,w2.z, b4.z)));
            v.w = fmaf(p0,w0.w, fmaf(p1,w1.w, fmaf(p2,w2.w, b4.w)));
            *(float4*)&net[rw*128 + cg] = v;
        }
    }
    __syncthreads();

    const uint32_t* A32h = (const uint32_t*)(sm + H_AH);
    const uint32_t* A32l = (const uint32_t*)(sm + H_AL);
    const uint32_t* W32h = (const uint32_t*)(sm + H_WH);
    const uint32_t* W32l = (const uint32_t*)(sm + H_WL);

    for (int i = 0; i < NB; i++) {
        { /* net += c @ fc_c[i] + b ; split relu(net) -> Ah/Al */
            float4 b4 = *(const float4*)&fcb[i*HD + cg];
            ull acc2[8][4];
#pragma unroll
            for (int rr = 0; rr < 8; rr++) {
                float4 v = *(const float4*)&net[(row0+rr)*128 + cg];
                acc2[rr][0] = pack2(v.x + b4.x, 0.f);
                acc2[rr][1] = pack2(v.y + b4.y, 0.f);
                acc2[rr][2] = pack2(v.z + b4.z, 0.f);
                acc2[rr][3] = pack2(v.w + b4.w, 0.f);
            }
#pragma unroll 2
            for (int k = 0; k < CD; k += 2) {
                float4 wa = __ldg((const float4*)&fcw[(i*CD + k)*HD + cg]);
                float4 wb = __ldg((const float4*)&fcw[(i*CD + k + 1)*HD + cg]);
                ull wx = pack2(wa.x, wb.x), wy = pack2(wa.y, wb.y);
                ull wz = pack2(wa.z, wb.z), ww = pack2(wa.w, wb.w);
#pragma unroll
                for (int rr = 0; rr < 8; rr++) {
                    ull a = *(const ull*)&cb[(row0+rr)*24 + k];
                    acc2[rr][0] = ffma2(a, wx, acc2[rr][0]);
                    acc2[rr][1] = ffma2(a, wy, acc2[rr][1]);
                    acc2[rr][2] = ffma2(a, wz, acc2[rr][2]);
                    acc2[rr][3] = ffma2(a, ww, acc2[rr][3]);
                }
            }
#pragma unroll
            for (int rr = 0; rr < 8; rr++) {
                int rw = row0 + rr;
                float2 f0 = unpack2(acc2[rr][0]), f1 = unpack2(acc2[rr][1]);
                float2 f2 = unpack2(acc2[rr][2]), f3 = unpack2(acc2[rr][3]);
                float4 v; v.x = f0.x+f0.y; v.y = f1.x+f1.y; v.z = f2.x+f2.y; v.w = f3.x+f3.y;
                *(float4*)&net[rw*128 + cg] = v;
                float ax = fmaxf(v.x,0.f), ay = fmaxf(v.y,0.f);
                float az = fmaxf(v.z,0.f), aw = fmaxf(v.w,0.f);
                __half hx = __float2half(ax), hy = __float2half(ay);
                __half hz = __float2half(az), hw = __float2half(aw);
                Ah2[rw*65 + (cg>>1)]     = __halves2half2(hx, hy);
                Ah2[rw*65 + (cg>>1) + 1] = __halves2half2(hz, hw);
                Al2[rw*65 + (cg>>1)]     = __halves2half2(__float2half(ax - __half2float(hx)),
                                                          __float2half(ay - __half2float(hy)));
                Al2[rw*65 + (cg>>1) + 1] = __halves2half2(__float2half(az - __half2float(hz)),
                                                          __float2half(aw - __half2float(hw)));
            }
        }
        { /* stage W0 hi/lo */
            const float* wb = b0w + (size_t)i*HD*HD;
            for (int e = t; e < HD*HD; e += 256) {
                float vv = wb[e];
                int k = e >> 7, n = e & 127;
                __half hi = __float2half(vv);
                WhH[n*130 + k] = hi;
                WlH[n*130 + k] = __float2half(vv - __half2float(hi));
            }
        }
        __syncthreads();
        /* mma blk0 */
        float d0[8][4];
#pragma unroll
        for (int nb = 0; nb < 8; nb++)
#pragma unroll
            for (int j = 0; j < 4; j++) d0[nb][j] = 0.f;
#pragma unroll
        for (int k0 = 0; k0 < 8; k0++) {
            int kc = k0*8 + tid;
            uint32_t ah0 = A32h[row*65 + kc],     ah1 = A32h[(row+8)*65 + kc];
            uint32_t ah2 = A32h[row*65 + kc + 4], ah3 = A32h[(row+8)*65 + kc + 4];
            uint32_t al0 = A32l[row*65 + kc],     al1 = A32l[(row+8)*65 + kc];
            uint32_t al2 = A32l[row*65 + kc + 4], al3 = A32l[(row+8)*65 + kc + 4];
#pragma unroll
            for (int nb = 0; nb < 8; nb++) {
                int nr = nh*64 + nb*8 + gid;
                uint32_t bh0 = W32h[nr*65 + kc], bh1 = W32h[nr*65 + kc + 4];
                uint32_t bl0 = W32l[nr*65 + kc], bl1 = W32l[nr*65 + kc + 4];
                mma16816(d0[nb], ah0, ah1, ah2, ah3, bh0, bh1);
                mma16816(d0[nb], ah0, ah1, ah2, ah3, bl0, bl1);
                mma16816(d0[nb], al0, al1, al2, al3, bh0, bh1);
            }
        }
        __syncthreads();
        /* epi0: hh = relu(d0+b0b) -> Ah/Al ; stage W1 */
#pragma unroll
        for (int nb = 0; nb < 8; nb++) {
            int col = nh*64 + nb*8 + tid*2;
            float bb0 = __ldg(&b0b[i*HD + col]);
            float bb1 = __ldg(&b0b[i*HD + col + 1]);
            float v0 = fmaxf(d0[nb][0] + bb0, 0.f);
            float v1 = fmaxf(d0[nb][1] + bb1, 0.f);
            float v2 = fmaxf(d0[nb][2] + bb0, 0.f);
            float v3 = fmaxf(d0[nb][3] + bb1, 0.f);
            __half h0 = __float2half(v0), h1 = __float2half(v1);
            __half h2 = __float2half(v2), h3 = __float2half(v3);
            Ah2[row*65 + (col>>1)]     = __halves2half2(h0, h1);
            Ah2[(row+8)*65 + (col>>1)] = __halves2half2(h2, h3);
            Al2[row*65 + (col>>1)]     = __halves2half2(__float2half(v0 - __half2float(h0)),
                                                        __float2half(v1 - __half2float(h1)));
            Al2[(row+8)*65 + (col>>1)] = __halves2half2(__float2half(v2 - __half2float(h2)),
                                                        __float2half(v3 - __half2float(h3)));
        }
        {
            const float* wb = b1w + (size_t)i*HD*HD;
            for (int e = t; e < HD*HD; e += 256) {
                float vv = wb[e];
                int k = e >> 7, n = e & 127;
                __half hi = __float2half(vv);
                WhH[n*130 + k] = hi;
                WlH[n*130 + k] = __float2half(vv - __half2float(hi));
            }
        }
        __syncthreads();
        /* mma blk1 */
        float d1[8][4];
#pragma unroll
        for (int nb = 0; nb < 8; nb++)
#pragma unroll
            for (int j = 0; j < 4; j++) d1[nb][j] = 0.f;
#pragma unroll
        for (int k0 = 0; k0 < 8; k0++) {
            int kc = k0*8 + tid;
            uint32_t ah0 = A32h[row*65 + kc],     ah1 = A32h[(row+8)*65 + kc];
            uint32_t ah2 = A32h[row*65 + kc + 4], ah3 = A32h[(row+8)*65 + kc + 4];
            uint32_t al0 = A32l[row*65 + kc],     al1 = A32l[(row+8)*65 + kc];
            uint32_t al2 = A32l[row*65 + kc + 4], al3 = A32l[(row+8)*65 + kc + 4];
#pragma unroll
            for (int nb = 0; nb < 8; nb++) {
                int nr = nh*64 + nb*8 + gid;
                uint32_t bh0 = W32h[nr*65 + kc], bh1 = W32h[nr*65 + kc + 4];
                uint32_t bl0 = W32l[nr*65 + kc], bl1 = W32l[nr*65 + kc + 4];
                mma16816(d1[nb], ah0, ah1, ah2, ah3, bh0, bh1);
                mma16816(d1[nb], ah0, ah1, ah2, ah3, bl0, bl1);
                mma16816(d1[nb], al0, al1, al2, al3, bh0, bh1);
            }
        }
        /* epi1: net += d1 + b1b */
#pragma unroll
        for (int nb = 0; nb < 8; nb++) {
            int col = nh*64 + nb*8 + tid*2;
            float bb0 = __ldg(&b1b[i*HD + col]);
            float bb1 = __ldg(&b1b[i*HD + col + 1]);
            net[row*128 + col]         += d1[nb][0] + bb0;
            net[row*128 + col + 1]     += d1[nb][1] + bb1;
            net[(row+8)*128 + col]     += d1[nb][2] + bb0;
            net[(row+8)*128 + col + 1] += d1[nb][3] + bb1;
        }
        __syncthreads();
    }

    if (t < 64) {
        float s = fob[0];
        for (int c2 = 0; c2 < HD; c2++)
            s = fmaf(fmaxf(net[t*128 + c2], 0.f), fo[c2], s);
        out[base + t] = s;
    }
}

/* ---------------- launch ---------------- */
extern "C" void kernel_launch(void* const* d_in, const int* in_sizes, int n_in,
                              void* d_out, int out_size) {
    (void)in_sizes; (void)n_in; (void)out_size;
    const float* p     = (const float*)d_in[0];
    const float* pc    = (const float*)d_in[1];
    const float* feat  = (const float*)d_in[2];
    const float* w1    = (const float*)d_in[3];
    const float* bn1g  = (const float*)d_in[4];
    const float* bn1b  = (const float*)d_in[5];
    const float* w2    = (const float*)d_in[6];
    const float* bn2g  = (const float*)d_in[7];
    const float* bn2b  = (const float*)d_in[8];
    const float* w3    = (const float*)d_in[9];
    const float* bn3g  = (const float*)d_in[10];
    const float* bn3b  = (const float*)d_in[11];
    const float* fpw   = (const float*)d_in[12];
    const float* fpb   = (const float*)d_in[13];
    const float* fcw   = (const float*)d_in[14];
    const float* fcb   = (const float*)d_in[15];
    const float* b0w   = (const float*)d_in[16];
    const float* b0b   = (const float*)d_in[17];
    const float* b1w   = (const float*)d_in[18];
    const float* b1b   = (const float*)d_in[19];
    const float* fow   = (const float*)d_in[20];
    const float* fob   = (const float*)d_in[21];
    float* out = (float*)d_out;

    cudaFuncSetAttribute(k_conv2,  cudaFuncAttributeMaxDynamicSharedMemorySize, C2_SMEM);
    cudaFuncSetAttribute(k_conv3p, cudaFuncAttributeMaxDynamicSharedMemorySize, SMEM3);
    cudaFuncSetAttribute(k_head,   cudaFuncAttributeMaxDynamicSharedMemorySize, SMEMH);

    float invN = 1.0f / (float)NROWS;

    k_pre<<<832, 256>>>(p, pc, feat, w1, w2);
    k_stats1<<<NROWS/512, 256>>>(bn1g, bn1b, invN);
    k_conv2<<<NROWS/128, 256, C2_SMEM>>>(bn2g, bn2b, invN);
    k_conv3p<<<NROWS/160, 192, SMEM3>>>(w3, bn3g, bn3b, invN);
    k_head<<<NPTS/64, 256, SMEMH>>>(p, fpw, fpb, fcw, fcb,
                                    b0w, b0b, b1w, b1b, fow, fob, out);
}

// round 16
// speedup vs baseline: 1.1683x; 1.1683x over previous
#include <cuda_runtime.h>
#include <cuda_fp16.h>
#include <math.h>
#include <stdint.h>

#define BSZ 4
#define NX 8192
#define NY 1024
#define KNN 20
#define CD 24
#define HD 128
#define NB 5
#define NROWS (BSZ*NX*KNN)   /* 655360 */
#define NPTS  (BSZ*NX)       /* 32768  */
#define BN_EPS 1e-5f

typedef unsigned long long ull;

/* ---------------- f32x2 packed helpers ---------------- */
__device__ __forceinline__ ull ffma2(ull a, ull b, ull c) {
    ull d;
    asm("fma.rn.f32x2 %0, %1, %2, %3;" : "=l"(d) : "l"(a), "l"(b), "l"(c));
    return d;
}
__device__ __forceinline__ ull pack2(float lo, float hi) {
    ull d;
    asm("mov.b64 %0, {%1, %2};" : "=l"(d) : "f"(lo), "f"(hi));
    return d;
}
__device__ __forceinline__ float2 unpack2(ull v) {
    float2 r;
    asm("mov.b64 {%0, %1}, %2;" : "=f"(r.x), "=f"(r.y) : "l"(v));
    return r;
}

/* ---------------- warp mma m16n8k16 f16 -> f32 ---------------- */
__device__ __forceinline__ void mma16816(float* d, uint32_t a0, uint32_t a1,
                                         uint32_t a2, uint32_t a3,
                                         uint32_t b0, uint32_t b1) {
    asm volatile(
        "mma.sync.aligned.m16n8k16.row.col.f32.f16.f16.f32 "
        "{%0,%1,%2,%3}, {%4,%5,%6,%7}, {%8,%9}, {%0,%1,%2,%3};"
        : "+f"(d[0]), "+f"(d[1]), "+f"(d[2]), "+f"(d[3])
        : "r"(a0), "r"(a1), "r"(a2), "r"(a3), "r"(b0), "r"(b1));
}

/* ---------------- scratch ---------------- */
__device__ int    g_idx[NROWS];                 /* 2.6 MB */
__device__ float  g_U[BSZ*NY*HD];               /* 2 MB   */
__device__ float  g_V[BSZ*NX*HD];               /* 16 MB  */
__device__ __half g_h2h[(size_t)NROWS*HD];      /* 168 MB */
__device__ float  g_pmax[NPTS*CD];              /* 3 MB   */
__device__ float  g_pmin[NPTS*CD];              /* 3 MB   */
__device__ __half g_W16[HD*HD];                 /* w2^T fp16 */
__device__ float  g_sum[3*HD];
__device__ float  g_sumsq[3*HD];
__device__ float  g_scale[3*HD];
__device__ float  g_shift[3*HD];
__device__ int    g_cnt[3];

__device__ __forceinline__ void bn_finalize(int L, int C, float invN,
                                            const float* g, const float* b, int c) {
    if (c < C) {
        float mean = g_sum[L*HD + c] * invN;
        float var  = g_sumsq[L*HD + c] * invN - mean*mean;
        float sc = g[c] * rsqrtf(var + BN_EPS);
        g_scale[L*HD + c] = sc;
        g_shift[L*HD + c] = b[c] - mean*sc;
    }
}

/* ---------------- top-20 insertion with tree-rescan ---------------- */
#define KNN_INSERT(dval, jval)                                                  \
    do {                                                                        \
        _Pragma("unroll")                                                       \
        for (int s = 0; s < KNN; s++) if (s == wpos) { bd[s] = (dval); bi[s] = (jval); } \
        float a0=fmaxf(bd[0],bd[1]),  a1=fmaxf(bd[2],bd[3]),  a2=fmaxf(bd[4],bd[5]);   \
        float a3=fmaxf(bd[6],bd[7]),  a4=fmaxf(bd[8],bd[9]),  a5=fmaxf(bd[10],bd[11]); \
        float a6=fmaxf(bd[12],bd[13]),a7=fmaxf(bd[14],bd[15]),a8=fmaxf(bd[16],bd[17]); \
        float a9=fmaxf(bd[18],bd[19]);                                          \
        float b0=fmaxf(a0,a1), b1=fmaxf(a2,a3), b2=fmaxf(a4,a5);                \
        float b3=fmaxf(a6,a7), b4=fmaxf(a8,a9);                                 \
        float c0=fmaxf(b0,b1), c1=fmaxf(b2,b3);                                 \
        worst = fmaxf(fmaxf(c0,c1), b4);                                        \
        _Pragma("unroll")                                                       \
        for (int s = 0; s < KNN; s++) wpos = (bd[s] == worst) ? s : wpos;       \
    } while (0)

/* ---------------- K1: KNN, 2-way split scan ----------------
   block = 128 points, 256 threads. half 0 scans j<512, half 1 scans j>=512,
   then half-1 results merged into half-0 via smem. */
__global__ void __launch_bounds__(256) k_knn(const float* __restrict__ p,
                                             const float* __restrict__ pc) {
    __shared__ float qx[NY], qy[NY], qz[NY], qn[NY];
    __shared__ float sd[128][KNN];
    __shared__ int   si[128][KNN];
    int b = blockIdx.y;
    int t = threadIdx.x;
    if (blockIdx.x == 0 && b == 0) {
        for (int c = t; c < 3*HD; c += 256) { g_sum[c] = 0.f; g_sumsq[c] = 0.f; }
        if (t < 3) g_cnt[t] = 0;
    }
    for (int j = t; j < NY; j += 256) {
        float x = pc[(b*NY + j)*3 + 0];
        float y = pc[(b*NY + j)*3 + 1];
        float z = pc[(b*NY + j)*3 + 2];
        qx[j] = x; qy[j] = y; qz[j] = z;
        qn[j] = x*x + y*y + z*z;
    }
    __syncthreads();

    int tid = t & 127, half = t >> 7;
    int n = blockIdx.x * 128 + tid;
    float px = p[(b*NX + n)*3 + 0];
    float py = p[(b*NX + n)*3 + 1];
    float pz = p[(b*NX + n)*3 + 2];
    float pn = px*px + py*py + pz*pz;

    float bd[KNN]; int bi[KNN];
#pragma unroll
    for (int s = 0; s < KNN; s++) { bd[s] = 3.4e38f; bi[s] = 0; }
    float worst = 3.4e38f; int wpos = 0;

    int j0 = half * 512;
    for (int jj = 0; jj < 512; jj++) {
        int j = j0 + jj;
        float d = pn + qn[j] - 2.f*(px*qx[j] + py*qy[j] + pz*qz[j]);
        if (d < worst) KNN_INSERT(d, j);
    }
    if (half) {
#pragma unroll
        for (int s = 0; s < KNN; s++) { sd[tid][s] = bd[s]; si[tid][s] = bi[s]; }
    }
    __syncthreads();
    if (!half) {
#pragma unroll
        for (int s2 = 0; s2 < KNN; s2++) {
            float d = sd[tid][s2];
            if (d < worst) { int j = si[tid][s2]; KNN_INSERT(d, j); }
        }
        int base = (b*NX + n)*KNN;
#pragma unroll
        for (int s = 0; s < KNN; s++) g_idx[base + s] = bi[s];
    }
}

/* ---------------- K2: fused preU + preV + prepW (R14-verified) -------------- */
__global__ void k_preUVW(const float* __restrict__ p, const float* __restrict__ pc,
                         const float* __restrict__ feat, const float* __restrict__ w1,
                         const float* __restrict__ w2) {
    int t = threadIdx.x;
    if (blockIdx.x < 128) {
        __shared__ float in_s[32][28];
        int base = blockIdx.x * 32;
        for (int e = t; e < 32*27; e += 128) {
            int r = e / 27, k = e % 27;
            int row = base + r;
            in_s[r][k] = (k < 3) ? pc[row*3 + k] : feat[row*24 + (k - 3)];
        }
        __syncthreads();
        float wr[27];
#pragma unroll
        for (int d = 0; d < 3; d++)  wr[d]     = w1[d*HD + t];
#pragma unroll
        for (int k = 0; k < 24; k++) wr[3 + k] = w1[(6 + k)*HD + t];
        for (int r = 0; r < 32; r++) {
            float acc = 0.f;
#pragma unroll
            for (int k = 0; k < 27; k++) acc = fmaf(in_s[r][k], wr[k], acc);
            g_U[(base + r)*HD + t] = acc;
        }
    } else if (blockIdx.x < 640) {
        __shared__ float ps[64][4];
        int base = (blockIdx.x - 128) * 64;
        for (int e = t; e < 64*3; e += 128) {
            int r = e / 3, d = e % 3;
            ps[r][d] = p[(base + r)*3 + d];
        }
        __syncthreads();
        float wd0 = w1[3*HD + t] - w1[0*HD + t];
        float wd1 = w1[4*HD + t] - w1[1*HD + t];
        float wd2 = w1[5*HD + t] - w1[2*HD + t];
        for (int r = 0; r < 64; r++) {
            float v = fmaf(ps[r][0], wd0, fmaf(ps[r][1], wd1, ps[r][2]*wd2));
            g_V[(base + r)*HD + t] = v;
        }
    } else {
        int e = (blockIdx.x - 640) * 128 + t;
        int n = e >> 7, k = e & 127;
        g_W16[e] = __float2half(w2[k*HD + n]);
    }
}

/* ---------------- K3: stats of h1 + fused finalize layer 0 ---------------- */
__global__ void k_stats1(const float* __restrict__ bn1g, const float* __restrict__ bn1b,
                         float invN) {
    __shared__ int uo[512], vo[512];
    __shared__ int lastflag;
    int blk = blockIdx.x, t = threadIdx.x;
    int base = blk * 512;
    for (int r = t; r < 512; r += 256) {
        int grow = base + r;
        int j = g_idx[grow];
        int b = grow / (NX*KNN);
        int n = (grow / KNN) % NX;
        uo[r] = (b*NY + j)*HD;
        vo[r] = (b*NX + n)*HD;
    }
    __syncthreads();
    int c = t & 127, rg = t >> 7;
    float s = 0.f, s2 = 0.f;
    for (int r = rg; r < 512; r += 2) {
        float v = g_U[uo[r] + c] + g_V[vo[r] + c];
        s += v; s2 += v*v;
    }
    atomicAdd(&g_sum[c], s);
    atomicAdd(&g_sumsq[c], s2);
    __threadfence();
    __syncthreads();
    if (t == 0) lastflag = (atomicAdd(&g_cnt[0], 1) == (int)gridDim.x - 1);
    __syncthreads();
    if (lastflag) bn_finalize(0, 128, invN, bn1g, bn1b, t);
}

/* ---------------- K4: conv2 via warp mma (verified) ---------------- */
#define C2_PH 136
#define C2_PW 68
#define C2_AS 2048
#define C2_BS (2048 + 34816)
#define C2_SMEM (2048 + 2*34816)
__global__ void __launch_bounds__(256) k_conv2(const float* __restrict__ bn2g,
                                               const float* __restrict__ bn2b,
                                               float invN) {
    extern __shared__ char smemraw[];
    float* sc = (float*)smemraw;
    float* sh = sc + 128;
    int*   uo = (int*)(sh + 128);
    int*   vo = uo + 128;
    __shared__ int lastflag;

    int t = threadIdx.x, blk = blockIdx.x;
    int lane = t & 31, wid = t >> 5;
    int rbase = blk * 128;
    __half* As = (__half*)(smemraw + C2_AS);
    __half* Bs = (__half*)(smemraw + C2_BS);

    if (t < 128) {
        int grow = rbase + t;
        int j = g_idx[grow];
        int b = grow / (NX*KNN);
        int n = (grow / KNN) % NX;
        uo[t] = (b*NY + j)*HD;
        vo[t] = (b*NX + n)*HD;
    } else {
        int c = t - 128;
        sc[c] = g_scale[c];
        sh[c] = g_shift[c];
    }
    __syncthreads();

    for (int e = t; e < HD*HD; e += 256) {
        int n = e >> 7, k = e & 127;
        Bs[n*C2_PH + k] = g_W16[e];
    }
    {
        int k = t & 127;
        for (int r = (t >> 7); r < 128; r += 2) {
            float v = g_U[uo[r] + k] + g_V[vo[r] + k];
            v = fmaf(sc[k], v, sh[k]);
            v = (v > 0.f) ? v : 0.2f*v;
            As[r*C2_PH + k] = __float2half(v);
        }
    }
    __syncthreads();

    const uint32_t* As32 = (const uint32_t*)As;
    const uint32_t* Bs32 = (const uint32_t*)Bs;
    int gid = lane >> 2, tid = lane & 3;
    int ar0 = wid*16 + gid;
    float d[16][4];
#pragma unroll
    for (int nb = 0; nb < 16; nb++)
#pragma unroll
        for (int j = 0; j < 4; j++) d[nb][j] = 0.f;

#pragma unroll
    for (int k0 = 0; k0 < 8; k0++) {
        int kc = k0*8 + tid;
        uint32_t a0 = As32[ar0*C2_PW + kc];
        uint32_t a1 = As32[(ar0+8)*C2_PW + kc];
        uint32_t a2 = As32[ar0*C2_PW + kc + 4];
        uint32_t a3 = As32[(ar0+8)*C2_PW + kc + 4];
#pragma unroll
        for (int nb = 0; nb < 16; nb++) {
            uint32_t b0 = Bs32[(nb*8+gid)*C2_PW + kc];
            uint32_t b1 = Bs32[(nb*8+gid)*C2_PW + kc + 4];
            mma16816(d[nb], a0, a1, a2, a3, b0, b1);
        }
    }
    __syncthreads();

    __half2* hst2 = (__half2*)(smemraw + C2_AS);
#pragma unroll
    for (int nb = 0; nb < 16; nb++) {
        hst2[ar0*C2_PW + nb*4 + tid]     = __floats2half2_rn(d[nb][0], d[nb][1]);
        hst2[(ar0+8)*C2_PW + nb*4 + tid] = __floats2half2_rn(d[nb][2], d[nb][3]);
    }
    __syncthreads();
    {
        __half2* dst = (__half2*)&g_h2h[(size_t)rbase*HD];
        for (int e = t; e < 128*64; e += 256) {
            int r = e >> 6, j = e & 63;
            dst[e] = hst2[r*C2_PW + j];
        }
    }
    {
        int c2 = t & 63, rg = t >> 6;
        float s0 = 0.f, q0 = 0.f, s1 = 0.f, q1 = 0.f;
        for (int r = rg*32; r < rg*32 + 32; r++) {
            float2 f = __half22float2(hst2[r*C2_PW + c2]);
            s0 += f.x; q0 += f.x*f.x;
            s1 += f.y; q1 += f.y*f.y;
        }
        atomicAdd(&g_sum[HD + 2*c2],     s0);
        atomicAdd(&g_sumsq[HD + 2*c2],   q0);
        atomicAdd(&g_sum[HD + 2*c2+1],   s1);
        atomicAdd(&g_sumsq[HD + 2*c2+1], q1);
    }
    __threadfence();
    __syncthreads();
    if (t == 0) lastflag = (atomicAdd(&g_cnt[1], 1) == (int)gridDim.x - 1);
    __syncthreads();
    if (lastflag) bn_finalize(1, 128, invN, bn2g, bn2b, t);
}

/* ---------------- K5: conv3 via warp mma (verified R14) + pool -------------- */
#define C3_AS 0
#define C3_WH 41600
#define C3_WL (41600 + 6272)
#define C3_H3 (41600 + 2*6272)
#define C3_SC (C3_H3 + 16000)
#define C3_SH (C3_SC + 512)
#define C3_RED (C3_SH + 512)
#define SMEM3 (C3_RED + 256)
__global__ void __launch_bounds__(192) k_conv3p(const float* __restrict__ w3,
                                                const float* __restrict__ bn3g,
                                                const float* __restrict__ bn3b,
                                                float invN) {
    extern __shared__ char smemraw[];
    __half* Wh = (__half*)(smemraw + C3_WH);
    __half* Wl = (__half*)(smemraw + C3_WL);
    float*  h3s = (float*)(smemraw + C3_H3);
    float*  sc = (float*)(smemraw + C3_SC);
    float*  sh = (float*)(smemraw + C3_SH);
    float*  red = (float*)(smemraw + C3_RED);
    __shared__ int lastflag;

    int t = threadIdx.x, blk = blockIdx.x;
    int lane = t & 31, w = t >> 5;
    int rbase = blk * 160;

    for (int e = t; e < 24*128; e += 192) {
        int n = e % 24, k = e / 24;
        float vv = w3[e];
        __half hi = __float2half(vv);
        Wh[n*130 + k] = hi;
        Wl[n*130 + k] = __float2half(vv - __half2float(hi));
    }
    if (t < 128) { sc[t] = g_scale[HD + t]; sh[t] = g_shift[HD + t]; }
    if (t < 48)  red[t] = 0.f;
    __syncthreads();
    {
        __half2* As2 = (__half2*)(smemraw + C3_AS);
        const __half2* hp = (const __half2*)g_h2h + (size_t)rbase*64;
        for (int e = t; e < 160*64; e += 192) {
            int r = e >> 6, kp = e & 63;
            float2 f = __half22float2(hp[(size_t)r*64 + kp]);
            int k0 = 2*kp;
            float v0 = fmaf(sc[k0],   f.x, sh[k0]);   v0 = (v0 > 0.f) ? v0 : 0.2f*v0;
            float v1 = fmaf(sc[k0+1], f.y, sh[k0+1]); v1 = (v1 > 0.f) ? v1 : 0.2f*v1;
            As2[r*65 + kp] = __floats2half2_rn(v0, v1);
        }
    }
    __syncthreads();

    const uint32_t* A32 = (const uint32_t*)(smemraw + C3_AS);
    const uint32_t* W32h = (const uint32_t*)(smemraw + C3_WH);
    const uint32_t* W32l = (const uint32_t*)(smemraw + C3_WL);
    int gid = lane >> 2, tid = lane & 3;
    int nb = w >> 1, mtb = (w & 1)*5;
    float d[5][4];
#pragma unroll
    for (int m = 0; m < 5; m++)
#pragma unroll
        for (int j = 0; j < 4; j++) d[m][j] = 0.f;

#pragma unroll
    for (int k0 = 0; k0 < 8; k0++) {
        int kc = k0*8 + tid;
        uint32_t bh0 = W32h[(nb*8+gid)*65 + kc];
        uint32_t bh1 = W32h[(nb*8+gid)*65 + kc + 4];
        uint32_t bl0 = W32l[(nb*8+gid)*65 + kc];
        uint32_t bl1 = W32l[(nb*8+gid)*65 + kc + 4];
#pragma unroll
        for (int m = 0; m < 5; m++) {
            int row = (mtb + m)*16 + gid;
            uint32_t a0 = A32[row*65 + kc];
            uint32_t a1 = A32[(row+8)*65 + kc];
            uint32_t a2 = A32[row*65 + kc + 4];
            uint32_t a3 = A32[(row+8)*65 + kc + 4];
            mma16816(d[m], a0, a1, a2, a3, bh0, bh1);
            mma16816(d[m], a0, a1, a2, a3, bl0, bl1);
        }
    }

    {
        int col = nb*8 + tid*2;
        float se = 0.f, qe = 0.f, so = 0.f, qo = 0.f;
#pragma unroll
        for (int m = 0; m < 5; m++) {
            int row = (mtb + m)*16 + gid;
            h3s[row*25 + col]       = d[m][0];
            h3s[row*25 + col+1]     = d[m][1];
            h3s[(row+8)*25 + col]   = d[m][2];
            h3s[(row+8)*25 + col+1] = d[m][3];
            se += d[m][0] + d[m][2]; qe += d[m][0]*d[m][0] + d[m][2]*d[m][2];
            so += d[m][1] + d[m][3]; qo += d[m][1]*d[m][1] + d[m][3]*d[m][3];
        }
        atomicAdd(&red[col], se);
        atomicAdd(&red[24 + col], qe);
        atomicAdd(&red[col+1], so);
        atomicAdd(&red[24 + col+1], qo);
    }
    __syncthreads();

    {
        int pl = t / 24, c2 = t % 24;
        float mx = -3.4e38f, mn = 3.4e38f;
#pragma unroll
        for (int kk = 0; kk < KNN; kk++) {
            float v = h3s[(pl*KNN + kk)*25 + c2];
            mx = fmaxf(mx, v); mn = fminf(mn, v);
        }
        int pt = blk*8 + pl;
        g_pmax[pt*24 + c2] = mx;
        g_pmin[pt*24 + c2] = mn;
    }
    if (t < 24) {
        atomicAdd(&g_sum[2*HD + t],   red[t]);
        atomicAdd(&g_sumsq[2*HD + t], red[24 + t]);
    }
    __threadfence();
    __syncthreads();
    if (t == 0) lastflag = (atomicAdd(&g_cnt[2], 1) == (int)gridDim.x - 1);
    __syncthreads();
    if (lastflag) bn_finalize(2, 24, invN, bn3g, bn3b, t);
}

/* ---------------- K6: ResNet-FC head: mma 3-term split (verified R14) ------- */
#define H_NET 0
#define H_AH  32768
#define H_AL  49408
#define H_WH  66048
#define H_WL  99328
#define H_CB  132608
#define H_PB  138752
#define H_FO  139520
#define SMEMH 140288
__global__ void __launch_bounds__(256) k_head(const float* __restrict__ p,
                       const float* __restrict__ fpw, const float* __restrict__ fpb,
                       const float* __restrict__ fcw, const float* __restrict__ fcb,
                       const float* __restrict__ b0w, const float* __restrict__ b0b,
                       const float* __restrict__ b1w, const float* __restrict__ b1b,
                       const float* __restrict__ fow, const float* __restrict__ fob,
                       float* __restrict__ out) {
    extern __shared__ char sm[];
    float*   net = (float*)(sm + H_NET);
    __half2* Ah2 = (__half2*)(sm + H_AH);
    __half2* Al2 = (__half2*)(sm + H_AL);
    __half*  WhH = (__half*)(sm + H_WH);
    __half*  WlH = (__half*)(sm + H_WL);
    float*   cb  = (float*)(sm + H_CB);
    float*   pb  = (float*)(sm + H_PB);
    float*   fo  = (float*)(sm + H_FO);

    int t = threadIdx.x, lane = t & 31, w = t >> 5;
    int gid = lane >> 2, tid = lane & 3;
    int mt = w & 3, nh = w >> 2;
    int row = mt*16 + gid;
    int base = blockIdx.x * 64;

    for (int e = t; e < 64*CD; e += 256) {
        int c2 = e % 24;
        float scv = g_scale[2*HD + c2], shv = g_shift[2*HD + c2];
        float v = (scv >= 0.f) ? g_pmax[base*24 + e] : g_pmin[base*24 + e];
        v = fmaf(scv, v, shv);
        cb[e] = (v > 0.f) ? v : 0.2f*v;
    }
    if (t < 192) pb[t] = p[base*3 + t];
    if (t < 128) fo[t] = fow[t];
    __syncthreads();

    int cg  = (t & 31) * 4;
    int row0 = (t >> 5) * 8;

    { /* net = p @ fc_p_w + b */
        float4 w0 = *(const float4*)&fpw[0*HD + cg];
        float4 w1 = *(const float4*)&fpw[1*HD + cg];
        float4 w2 = *(const float4*)&fpw[2*HD + cg];
        float4 b4 = *(const float4*)&fpb[cg];
#pragma unroll
        for (int rr = 0; rr < 8; rr++) {
            int rw = row0 + rr;
            float p0 = pb[rw*3+0], p1 = pb[rw*3+1], p2 = pb[rw*3+2];
            float4 v;
            v.x = fmaf(p0,w0.x, fmaf(p1,w1.x, fmaf(p2,w2.x, b4.x)));
            v.y = fmaf(p0,w0.y, fmaf(p1,w1.y, fmaf(p2,w2.y, b4.y)));
            v.z = fmaf(p0,w0.z, fmaf(p1,w1.z, fmaf(p2,w2.z, b4.z)));
            v.w = fmaf(p0,w0.w, fmaf(p1,w1.w, fmaf(p2,w2.w, b4.w)));
            *(float4*)&net[rw*128 + cg] = v;
        }
    }
    __syncthreads();

    const uint32_t* A32h = (const uint32_t*)(sm + H_AH);
    const uint32_t* A32l = (const uint32_t*)(sm + H_AL);
    const uint32_t* W32h = (const uint32_t*)(sm + H_WH);
    const uint32_t* W32l = (const uint32_t*)(sm + H_WL);

    for (int i = 0; i < NB; i++) {
        { /* net += c @ fc_c[i] + b ; split relu(net) -> Ah/Al */
            float4 b4 = *(const float4*)&fcb[i*HD + cg];
            ull acc2[8][4];
#pragma unroll
            for (int rr = 0; rr < 8; rr++) {
                float4 v = *(const float4*)&net[(row0+rr)*128 + cg];
                acc2[rr][0] = pack2(v.x + b4.x, 0.f);
                acc2[rr][1] = pack2(v.y + b4.y, 0.f);
                acc2[rr][2] = pack2(v.z + b4.z, 0.f);
                acc2[rr][3] = pack2(v.w + b4.w, 0.f);
            }
#pragma unroll 2
            for (int k = 0; k < CD; k += 2) {
                float4 wa = __ldg((const float4*)&fcw[(i*CD + k)*HD + cg]);
                float4 wb = __ldg((const float4*)&fcw[(i*CD + k + 1)*HD + cg]);
                ull wx = pack2(wa.x, wb.x), wy = pack2(wa.y, wb.y);
                ull wz = pack2(wa.z, wb.z), ww = pack2(wa.w, wb.w);
#pragma unroll
                for (int rr = 0; rr < 8; rr++) {
                    ull a = *(const ull*)&cb[(row0+rr)*24 + k];
                    acc2[rr][0] = ffma2(a, wx, acc2[rr][0]);
                    acc2[rr][1] = ffma2(a, wy, acc2[rr][1]);
                    acc2[rr][2] = ffma2(a, wz, acc2[rr][2]);
                    acc2[rr][3] = ffma2(a, ww, acc2[rr][3]);
                }
            }
#pragma unroll
            for (int rr = 0; rr < 8; rr++) {
                int rw = row0 + rr;
                float2 f0 = unpack2(acc2[rr][0]), f1 = unpack2(acc2[rr][1]);
                float2 f2 = unpack2(acc2[rr][2]), f3 = unpack2(acc2[rr][3]);
                float4 v; v.x = f0.x+f0.y; v.y = f1.x+f1.y; v.z = f2.x+f2.y; v.w = f3.x+f3.y;
                *(float4*)&net[rw*128 + cg] = v;
                float ax = fmaxf(v.x,0.f), ay = fmaxf(v.y,0.f);
                float az = fmaxf(v.z,0.f), aw = fmaxf(v.w,0.f);
                __half hx = __float2half(ax), hy = __float2half(ay);
                __half hz = __float2half(az), hw = __float2half(aw);
                Ah2[rw*65 + (cg>>1)]     = __halves2half2(hx, hy);
                Ah2[rw*65 + (cg>>1) + 1] = __halves2half2(hz, hw);
                Al2[rw*65 + (cg>>1)]     = __halves2half2(__float2half(ax - __half2float(hx)),
                                                          __float2half(ay - __half2float(hy)));
                Al2[rw*65 + (cg>>1) + 1] = __halves2half2(__float2half(az - __half2float(hz)),
                                                          __float2half(aw - __half2float(hw)));
            }
        }
        { /* stage W0 hi/lo */
            const float* wb = b0w + (size_t)i*HD*HD;
            for (int e = t; e < HD*HD; e += 256) {
                float vv = wb[e];
                int k = e >> 7, n = e & 127;
                __half hi = __float2half(vv);
                WhH[n*130 + k] = hi;
                WlH[n*130 + k] = __float2half(vv - __half2float(hi));
            }
        }
        __syncthreads();
        /* mma blk0 */
        float d0[8][4];
#pragma unroll
        for (int nb = 0; nb < 8; nb++)
#pragma unroll
            for (int j = 0; j < 4; j++) d0[nb][j] = 0.f;
#pragma unroll
        for (int k0 = 0; k0 < 8; k0++) {
            int kc = k0*8 + tid;
            uint32_t ah0 = A32h[row*65 + kc],     ah1 = A32h[(row+8)*65 + kc];
            uint32_t ah2 = A32h[row*65 + kc + 4], ah3 = A32h[(row+8)*65 + kc + 4];
            uint32_t al0 = A32l[row*65 + kc],     al1 = A32l[(row+8)*65 + kc];
            uint32_t al2 = A32l[row*65 + kc + 4], al3 = A32l[(row+8)*65 + kc + 4];
#pragma unroll
            for (int nb = 0; nb < 8; nb++) {
                int nr = nh*64 + nb*8 + gid;
                uint32_t bh0 = W32h[nr*65 + kc], bh1 = W32h[nr*65 + kc + 4];
                uint32_t bl0 = W32l[nr*65 + kc], bl1 = W32l[nr*65 + kc + 4];
                mma16816(d0[nb], ah0, ah1, ah2, ah3, bh0, bh1);
                mma16816(d0[nb], ah0, ah1, ah2, ah3, bl0, bl1);
                mma16816(d0[nb], al0, al1, al2, al3, bh0, bh1);
            }
        }
        __syncthreads();
        /* epi0: hh = relu(d0+b0b) -> Ah/Al ; stage W1 */
#pragma unroll
        for (int nb = 0; nb < 8; nb++) {
            int col = nh*64 + nb*8 + tid*2;
            float bb0 = __ldg(&b0b[i*HD + col]);
            float bb1 = __ldg(&b0b[i*HD + col + 1]);
            float v0 = fmaxf(d0[nb][0] + bb0, 0.f);
            float v1 = fmaxf(d0[nb][1] + bb1, 0.f);
            float v2 = fmaxf(d0[nb][2] + bb0, 0.f);
            float v3 = fmaxf(d0[nb][3] + bb1, 0.f);
            __half h0 = __float2half(v0), h1 = __float2half(v1);
            __half h2 = __float2half(v2), h3 = __float2half(v3);
            Ah2[row*65 + (col>>1)]     = __halves2half2(h0, h1);
            Ah2[(row+8)*65 + (col>>1)] = __halves2half2(h2, h3);
            Al2[row*65 + (col>>1)]     = __halves2half2(__float2half(v0 - __half2float(h0)),
                                                        __float2half(v1 - __half2float(h1)));
            Al2[(row+8)*65 + (col>>1)] = __halves2half2(__float2half(v2 - __half2float(h2)),
                                                        __float2half(v3 - __half2float(h3)));
        }
        {
            const float* wb = b1w + (size_t)i*HD*HD;
            for (int e = t; e < HD*HD; e += 256) {
                float vv = wb[e];
                int k = e >> 7, n = e & 127;
                __half hi = __float2half(vv);
                WhH[n*130 + k] = hi;
                WlH[n*130 + k] = __float2half(vv - __half2float(hi));
            }
        }
        __syncthreads();
        /* mma blk1 */
        float d1[8][4];
#pragma unroll
        for (int nb = 0; nb < 8; nb++)
#pragma unroll
            for (int j = 0; j < 4; j++) d1[nb][j] = 0.f;
#pragma unroll
        for (int k0 = 0; k0 < 8; k0++) {
            int kc = k0*8 + tid;
            uint32_t ah0 = A32h[row*65 + kc],     ah1 = A32h[(row+8)*65 + kc];
            uint32_t ah2 = A32h[row*65 + kc + 4], ah3 = A32h[(row+8)*65 + kc + 4];
            uint32_t al0 = A32l[row*65 + kc],     al1 = A32l[(row+8)*65 + kc];
            uint32_t al2 = A32l[row*65 + kc + 4], al3 = A32l[(row+8)*65 + kc + 4];
#pragma unroll
            for (int nb = 0; nb < 8; nb++) {
                int nr = nh*64 + nb*8 + gid;
                uint32_t bh0 = W32h[nr*65 + kc], bh1 = W32h[nr*65 + kc + 4];
                uint32_t bl0 = W32l[nr*65 + kc], bl1 = W32l[nr*65 + kc + 4];
                mma16816(d1[nb], ah0, ah1, ah2, ah3, bh0, bh1);
                mma16816(d1[nb], ah0, ah1, ah2, ah3, bl0, bl1);
                mma16816(d1[nb], al0, al1, al2, al3, bh0, bh1);
            }
        }
        /* epi1: net += d1 + b1b */
#pragma unroll
        for (int nb = 0; nb < 8; nb++) {
            int col = nh*64 + nb*8 + tid*2;
            float bb0 = __ldg(&b1b[i*HD + col]);
            float bb1 = __ldg(&b1b[i*HD + col + 1]);
            net[row*128 + col]         += d1[nb][0] + bb0;
            net[row*128 + col + 1]     += d1[nb][1] + bb1;
            net[(row+8)*128 + col]     += d1[nb][2] + bb0;
            net[(row+8)*128 + col + 1] += d1[nb][3] + bb1;
        }
        __syncthreads();
    }

    if (t < 64) {
        float s = fob[0];
        for (int c2 = 0; c2 < HD; c2++)
            s = fmaf(fmaxf(net[t*128 + c2], 0.f), fo[c2], s);
        out[base + t] = s;
    }
}

/* ---------------- launch ---------------- */
extern "C" void kernel_launch(void* const* d_in, const int* in_sizes, int n_in,
                              void* d_out, int out_size) {
    (void)in_sizes; (void)n_in; (void)out_size;
    const float* p     = (const float*)d_in[0];
    const float* pc    = (const float*)d_in[1];
    const float* feat  = (const float*)d_in[2];
    const float* w1    = (const float*)d_in[3];
    const float* bn1g  = (const float*)d_in[4];
    const float* bn1b  = (const float*)d_in[5];
    const float* w2    = (const float*)d_in[6];
    const float* bn2g  = (const float*)d_in[7];
    const float* bn2b  = (const float*)d_in[8];
    const float* w3    = (const float*)d_in[9];
    const float* bn3g  = (const float*)d_in[10];
    const float* bn3b  = (const float*)d_in[11];
    const float* fpw   = (const float*)d_in[12];
    const float* fpb   = (const float*)d_in[13];
    const float* fcw   = (const float*)d_in[14];
    const float* fcb   = (const float*)d_in[15];
    const float* b0w   = (const float*)d_in[16];
    const float* b0b   = (const float*)d_in[17];
    const float* b1w   = (const float*)d_in[18];
    const float* b1b   = (const float*)d_in[19];
    const float* fow   = (const float*)d_in[20];
    const float* fob   = (const float*)d_in[21];
    float* out = (float*)d_out;

    cudaFuncSetAttribute(k_conv2,  cudaFuncAttributeMaxDynamicSharedMemorySize, C2_SMEM);
    cudaFuncSetAttribute(k_conv3p, cudaFuncAttributeMaxDynamicSharedMemorySize, SMEM3);
    cudaFuncSetAttribute(k_head,   cudaFuncAttributeMaxDynamicSharedMemorySize, SMEMH);

    float invN = 1.0f / (float)NROWS;

    k_knn<<<dim3(NX/128, BSZ), 256>>>(p, pc);
    k_preUVW<<<768, 128>>>(p, pc, feat, w1, w2);
    k_stats1<<<NROWS/512, 256>>>(bn1g, bn1b, invN);
    k_conv2<<<NROWS/128, 256, C2_SMEM>>>(bn2g, bn2b, invN);
    k_conv3p<<<NROWS/160, 192, SMEM3>>>(w3, bn3g, bn3b, invN);
    k_head<<<NPTS/64, 256, SMEMH>>>(p, fpw, fpb, fcw, fcb,
                                    b0w, b0b, b1w, b1b, fow, fob, out);
}

// round 17
// speedup vs baseline: 1.2156x; 1.0404x over previous
#include <cuda_runtime.h>
#include <cuda_fp16.h>
#include <math.h>
#include <stdint.h>

#define BSZ 4
#define NX 8192
#define NY 1024
#define KNN 20
#define CD 24
#define HD 128
#define NB 5
#define NROWS (BSZ*NX*KNN)   /* 655360 */
#define NPTS  (BSZ*NX)       /* 32768  */
#define BN_EPS 1e-5f

typedef unsigned long long ull;

/* ---------------- f32x2 packed helpers ---------------- */
__device__ __forceinline__ ull ffma2(ull a, ull b, ull c) {
    ull d;
    asm("fma.rn.f32x2 %0, %1, %2, %3;" : "=l"(d) : "l"(a), "l"(b), "l"(c));
    return d;
}
__device__ __forceinline__ ull pack2(float lo, float hi) {
    ull d;
    asm("mov.b64 %0, {%1, %2};" : "=l"(d) : "f"(lo), "f"(hi));
    return d;
}
__device__ __forceinline__ float2 unpack2(ull v) {
    float2 r;
    asm("mov.b64 {%0, %1}, %2;" : "=f"(r.x), "=f"(r.y) : "l"(v));
    return r;
}

/* ---------------- warp mma m16n8k16 f16 -> f32 ---------------- */
__device__ __forceinline__ void mma16816(float* d, uint32_t a0, uint32_t a1,
                                         uint32_t a2, uint32_t a3,
                                         uint32_t b0, uint32_t b1) {
    asm volatile(
        "mma.sync.aligned.m16n8k16.row.col.f32.f16.f16.f32 "
        "{%0,%1,%2,%3}, {%4,%5,%6,%7}, {%8,%9}, {%0,%1,%2,%3};"
        : "+f"(d[0]), "+f"(d[1]), "+f"(d[2]), "+f"(d[3])
        : "r"(a0), "r"(a1), "r"(a2), "r"(a3), "r"(b0), "r"(b1));
}

/* ---------------- scratch ---------------- */
__device__ int    g_idx[NROWS];                 /* 2.6 MB */
__device__ float  g_U[BSZ*NY*HD];               /* 2 MB   */
__device__ float  g_V[BSZ*NX*HD];               /* 16 MB  */
__device__ __half g_h2h[(size_t)NROWS*HD];      /* 168 MB */
__device__ float  g_pmax[NPTS*CD];              /* 3 MB   */
__device__ float  g_pmin[NPTS*CD];              /* 3 MB   */
__device__ __half g_W16[HD*HD];                 /* w2^T fp16 */
__device__ float  g_sum[3*HD];
__device__ float  g_sumsq[3*HD];
__device__ float  g_scale[3*HD];
__device__ float  g_shift[3*HD];
__device__ int    g_cnt[3];

__device__ __forceinline__ void bn_finalize(int L, int C, float invN,
                                            const float* g, const float* b, int c) {
    if (c < C) {
        float mean = g_sum[L*HD + c] * invN;
        float var  = g_sumsq[L*HD + c] * invN - mean*mean;
        float sc = g[c] * rsqrtf(var + BN_EPS);
        g_scale[L*HD + c] = sc;
        g_shift[L*HD + c] = b[c] - mean*sc;
    }
}

/* ---------------- K1a: preU ---------------- */
__global__ void k_preU(const float* __restrict__ pc, const float* __restrict__ feat,
                       const float* __restrict__ w1) {
    __shared__ float in_s[32][28];
    int base = blockIdx.x * 32;
    int t = threadIdx.x;
    for (int e = t; e < 32*27; e += 128) {
        int r = e / 27, k = e % 27;
        int row = base + r;
        in_s[r][k] = (k < 3) ? pc[row*3 + k] : feat[row*24 + (k - 3)];
    }
    __syncthreads();
    float wr[27];
#pragma unroll
    for (int d = 0; d < 3; d++)  wr[d]     = w1[d*HD + t];
#pragma unroll
    for (int k = 0; k < 24; k++) wr[3 + k] = w1[(6 + k)*HD + t];
    for (int r = 0; r < 32; r++) {
        float acc = 0.f;
#pragma unroll
        for (int k = 0; k < 27; k++) acc = fmaf(in_s[r][k], wr[k], acc);
        g_U[(base + r)*HD + t] = acc;
    }
}

/* ---------------- K1b: preV ---------------- */
__global__ void k_preV(const float* __restrict__ p, const float* __restrict__ w1) {
    __shared__ float ps[64][4];
    int base = blockIdx.x * 64;
    int t = threadIdx.x;
    for (int e = t; e < 64*3; e += 128) {
        int r = e / 3, d = e % 3;
        ps[r][d] = p[(base + r)*3 + d];
    }
    __syncthreads();
    float wd0 = w1[3*HD + t] - w1[0*HD + t];
    float wd1 = w1[4*HD + t] - w1[1*HD + t];
    float wd2 = w1[5*HD + t] - w1[2*HD + t];
    for (int r = 0; r < 64; r++) {
        float v = fmaf(ps[r][0], wd0, fmaf(ps[r][1], wd1, ps[r][2]*wd2));
        g_V[(base + r)*HD + t] = v;
    }
}

/* ---------------- K1c: prepW ---------------- */
__global__ void k_preW(const float* __restrict__ w2) {
    int e = blockIdx.x * 128 + threadIdx.x;
    int n = e >> 7, k = e & 127;
    g_W16[e] = __float2half(w2[k*HD + n]);
}

/* ---------------- top-20 insertion with tree-rescan ---------------- */
#define KNN_INSERT(dval, jval)                                                  \
    do {                                                                        \
        _Pragma("unroll")                                                       \
        for (int s = 0; s < KNN; s++) if (s == wpos) { bd[s] = (dval); bi[s] = (jval); } \
        float a0=fmaxf(bd[0],bd[1]),  a1=fmaxf(bd[2],bd[3]),  a2=fmaxf(bd[4],bd[5]);   \
        float a3=fmaxf(bd[6],bd[7]),  a4=fmaxf(bd[8],bd[9]),  a5=fmaxf(bd[10],bd[11]); \
        float a6=fmaxf(bd[12],bd[13]),a7=fmaxf(bd[14],bd[15]),a8=fmaxf(bd[16],bd[17]); \
        float a9=fmaxf(bd[18],bd[19]);                                          \
        float b0=fmaxf(a0,a1), b1=fmaxf(a2,a3), b2=fmaxf(a4,a5);                \
        float b3=fmaxf(a6,a7), b4=fmaxf(a8,a9);                                 \
        float c0=fmaxf(b0,b1), c1=fmaxf(b2,b3);                                 \
        worst = fmaxf(fmaxf(c0,c1), b4);                                        \
        _Pragma("unroll")                                                       \
        for (int s = 0; s < KNN; s++) wpos = (bd[s] == worst) ? s : wpos;       \
    } while (0)

/* ---------------- K2: KNN, 2-way split scan (launch #4 => profiled) -------- */
__global__ void __launch_bounds__(256) k_knn(const float* __restrict__ p,
                                             const float* __restrict__ pc) {
    __shared__ float qx[NY], qy[NY], qz[NY], qn[NY];
    __shared__ float sd[128][KNN];
    __shared__ int   si[128][KNN];
    int b = blockIdx.y;
    int t = threadIdx.x;
    if (blockIdx.x == 0 && b == 0) {
        for (int c = t; c < 3*HD; c += 256) { g_sum[c] = 0.f; g_sumsq[c] = 0.f; }
        if (t < 3) g_cnt[t] = 0;
    }
    for (int j = t; j < NY; j += 256) {
        float x = pc[(b*NY + j)*3 + 0];
        float y = pc[(b*NY + j)*3 + 1];
        float z = pc[(b*NY + j)*3 + 2];
        qx[j] = x; qy[j] = y; qz[j] = z;
        qn[j] = x*x + y*y + z*z;
    }
    __syncthreads();

    int tid = t & 127, half = t >> 7;
    int n = blockIdx.x * 128 + tid;
    float px = p[(b*NX + n)*3 + 0];
    float py = p[(b*NX + n)*3 + 1];
    float pz = p[(b*NX + n)*3 + 2];
    float pn = px*px + py*py + pz*pz;

    float bd[KNN]; int bi[KNN];
#pragma unroll
    for (int s = 0; s < KNN; s++) { bd[s] = 3.4e38f; bi[s] = 0; }
    float worst = 3.4e38f; int wpos = 0;

    int j0 = half * 512;
    for (int jj = 0; jj < 512; jj++) {
        int j = j0 + jj;
        float d = pn + qn[j] - 2.f*(px*qx[j] + py*qy[j] + pz*qz[j]);
        if (d < worst) KNN_INSERT(d, j);
    }
    if (half) {
#pragma unroll
        for (int s = 0; s < KNN; s++) { sd[tid][s] = bd[s]; si[tid][s] = bi[s]; }
    }
    __syncthreads();
    if (!half) {
#pragma unroll
        for (int s2 = 0; s2 < KNN; s2++) {
            float d = sd[tid][s2];
            if (d < worst) { int j = si[tid][s2]; KNN_INSERT(d, j); }
        }
        int base = (b*NX + n)*KNN;
#pragma unroll
        for (int s = 0; s < KNN; s++) g_idx[base + s] = bi[s];
    }
}

/* ---------------- K3: stats of h1 + fused finalize layer 0 ---------------- */
__global__ void k_stats1(const float* __restrict__ bn1g, const float* __restrict__ bn1b,
                         float invN) {
    __shared__ int uo[512], vo[512];
    __shared__ int lastflag;
    int blk = blockIdx.x, t = threadIdx.x;
    int base = blk * 512;
    for (int r = t; r < 512; r += 256) {
        int grow = base + r;
        int j = g_idx[grow];
        int b = grow / (NX*KNN);
        int n = (grow / KNN) % NX;
        uo[r] = (b*NY + j)*HD;
        vo[r] = (b*NX + n)*HD;
    }
    __syncthreads();
    int c = t & 127, rg = t >> 7;
    float s = 0.f, s2 = 0.f;
    for (int r = rg; r < 512; r += 2) {
        float v = g_U[uo[r] + c] + g_V[vo[r] + c];
        s += v; s2 += v*v;
    }
    atomicAdd(&g_sum[c], s);
    atomicAdd(&g_sumsq[c], s2);
    __threadfence();
    __syncthreads();
    if (t == 0) lastflag = (atomicAdd(&g_cnt[0], 1) == (int)gridDim.x - 1);
    __syncthreads();
    if (lastflag) bn_finalize(0, 128, invN, bn1g, bn1b, t);
}

/* ---------------- K4: conv2 via warp mma (vectorized memory phases) --------- */
#define C2_PH 136
#define C2_PW 68
#define C2_AS 2048
#define C2_BS (2048 + 34816)
#define C2_SMEM (2048 + 2*34816)
__global__ void __launch_bounds__(256) k_conv2(const float* __restrict__ bn2g,
                                               const float* __restrict__ bn2b,
                                               float invN) {
    extern __shared__ char smemraw[];
    float* sc = (float*)smemraw;
    float* sh = sc + 128;
    int*   uo = (int*)(sh + 128);
    int*   vo = uo + 128;
    __shared__ int lastflag;

    int t = threadIdx.x, blk = blockIdx.x;
    int lane = t & 31, wid = t >> 5;
    int rbase = blk * 128;
    __half* As = (__half*)(smemraw + C2_AS);
    __half* Bs = (__half*)(smemraw + C2_BS);

    if (t < 128) {
        int grow = rbase + t;
        int j = g_idx[grow];
        int b = grow / (NX*KNN);
        int n = (grow / KNN) % NX;
        uo[t] = (b*NY + j)*HD;
        vo[t] = (b*NX + n)*HD;
    } else {
        int c = t - 128;
        sc[c] = g_scale[c];
        sh[c] = g_shift[c];
    }
    __syncthreads();

    /* stage B: uint4 loads (L2) + STS.128 (pitch 272B: 16B-aligned) */
    {
        const uint4* w4 = (const uint4*)g_W16;
        for (int e = t; e < HD*HD/8; e += 256) {
            int n = e >> 4, q = e & 15;
            *(uint4*)&Bs[n*C2_PH + q*8] = w4[e];
        }
    }
    /* stage A: float4 U/V gather -> bn1+lrelu -> fp16 (8B stores) */
    {
        int kq = (t & 31) * 4;
        float4 s4 = *(const float4*)&sc[kq];
        float4 h4 = *(const float4*)&sh[kq];
        for (int r = (t >> 5); r < 128; r += 8) {
            float4 u = *(const float4*)&g_U[uo[r] + kq];
            float4 vv = *(const float4*)&g_V[vo[r] + kq];
            float v0 = fmaf(s4.x, u.x + vv.x, h4.x); v0 = (v0 > 0.f) ? v0 : 0.2f*v0;
            float v1 = fmaf(s4.y, u.y + vv.y, h4.y); v1 = (v1 > 0.f) ? v1 : 0.2f*v1;
            float v2 = fmaf(s4.z, u.z + vv.z, h4.z); v2 = (v2 > 0.f) ? v2 : 0.2f*v2;
            float v3 = fmaf(s4.w, u.w + vv.w, h4.w); v3 = (v3 > 0.f) ? v3 : 0.2f*v3;
            __half2* dst = (__half2*)&As[r*C2_PH + kq];
            dst[0] = __floats2half2_rn(v0, v1);
            dst[1] = __floats2half2_rn(v2, v3);
        }
    }
    __syncthreads();

    const uint32_t* As32 = (const uint32_t*)As;
    const uint32_t* Bs32 = (const uint32_t*)Bs;
    int gid = lane >> 2, tid = lane & 3;
    int ar0 = wid*16 + gid;
    float d[16][4];
#pragma unroll
    for (int nb = 0; nb < 16; nb++)
#pragma unroll
        for (int j = 0; j < 4; j++) d[nb][j] = 0.f;

#pragma unroll
    for (int k0 = 0; k0 < 8; k0++) {
        int kc = k0*8 + tid;
        uint32_t a0 = As32[ar0*C2_PW + kc];
        uint32_t a1 = As32[(ar0+8)*C2_PW + kc];
        uint32_t a2 = As32[ar0*C2_PW + kc + 4];
        uint32_t a3 = As32[(ar0+8)*C2_PW + kc + 4];
#pragma unroll
        for (int nb = 0; nb < 16; nb++) {
            uint32_t b0 = Bs32[(nb*8+gid)*C2_PW + kc];
            uint32_t b1 = Bs32[(nb*8+gid)*C2_PW + kc + 4];
            mma16816(d[nb], a0, a1, a2, a3, b0, b1);
        }
    }
    __syncthreads();

    __half2* hst2 = (__half2*)(smemraw + C2_AS);
#pragma unroll
    for (int nb = 0; nb < 16; nb++) {
        hst2[ar0*C2_PW + nb*4 + tid]     = __floats2half2_rn(d[nb][0], d[nb][1]);
        hst2[(ar0+8)*C2_PW + nb*4 + tid] = __floats2half2_rn(d[nb][2], d[nb][3]);
    }
    __syncthreads();
    /* h2 store: uint4 (row = 16 uint4 data, pitch 17 uint4) */
    {
        uint4* dst = (uint4*)&g_h2h[(size_t)rbase*HD];
        const uint4* src = (const uint4*)hst2;
        for (int e = t; e < 128*16; e += 256) {
            int r = e >> 4, j = e & 15;
            dst[e] = src[r*17 + j];
        }
    }
    {
        int c2 = t & 63, rg = t >> 6;
        float s0 = 0.f, q0 = 0.f, s1 = 0.f, q1 = 0.f;
        for (int r = rg*32; r < rg*32 + 32; r++) {
            float2 f = __half22float2(hst2[r*C2_PW + c2]);
            s0 += f.x; q0 += f.x*f.x;
            s1 += f.y; q1 += f.y*f.y;
        }
        atomicAdd(&g_sum[HD + 2*c2],     s0);
        atomicAdd(&g_sumsq[HD + 2*c2],   q0);
        atomicAdd(&g_sum[HD + 2*c2+1],   s1);
        atomicAdd(&g_sumsq[HD + 2*c2+1], q1);
    }
    __threadfence();
    __syncthreads();
    if (t == 0) lastflag = (atomicAdd(&g_cnt[1], 1) == (int)gridDim.x - 1);
    __syncthreads();
    if (lastflag) bn_finalize(1, 128, invN, bn2g, bn2b, t);
}

/* ---------------- K5: conv3 via warp mma + pool (uint4 h2 loads) ------------ */
#define C3_AS 0
#define C3_WH 41600
#define C3_WL (41600 + 6272)
#define C3_H3 (41600 + 2*6272)
#define C3_SC (C3_H3 + 16000)
#define C3_SH (C3_SC + 512)
#define C3_RED (C3_SH + 512)
#define SMEM3 (C3_RED + 256)
__global__ void __launch_bounds__(192) k_conv3p(const float* __restrict__ w3,
                                                const float* __restrict__ bn3g,
                                                const float* __restrict__ bn3b,
                                                float invN) {
    extern __shared__ char smemraw[];
    __half* Wh = (__half*)(smemraw + C3_WH);
    __half* Wl = (__half*)(smemraw + C3_WL);
    float*  h3s = (float*)(smemraw + C3_H3);
    float*  sc = (float*)(smemraw + C3_SC);
    float*  sh = (float*)(smemraw + C3_SH);
    float*  red = (float*)(smemraw + C3_RED);
    __shared__ int lastflag;

    int t = threadIdx.x, blk = blockIdx.x;
    int lane = t & 31, w = t >> 5;
    int rbase = blk * 160;

    for (int e = t; e < 24*128; e += 192) {
        int n = e % 24, k = e / 24;
        float vv = w3[e];
        __half hi = __float2half(vv);
        Wh[n*130 + k] = hi;
        Wl[n*130 + k] = __float2half(vv - __half2float(hi));
    }
    if (t < 128) { sc[t] = g_scale[HD + t]; sh[t] = g_shift[HD + t]; }
    if (t < 48)  red[t] = 0.f;
    __syncthreads();
    /* stage A: uint4 h2 loads -> bn2+lrelu -> fp16 */
    {
        __half2* As2 = (__half2*)(smemraw + C3_AS);
        const uint4* hp4 = (const uint4*)(g_h2h + (size_t)rbase*HD);
        for (int e = t; e < 160*16; e += 192) {
            int r = e >> 4, q = e & 15;
            uint4 raw = hp4[e];
            const __half2* hin = (const __half2*)&raw;
            int k0 = q*8;
#pragma unroll
            for (int jj = 0; jj < 4; jj++) {
                float2 f = __half22float2(hin[jj]);
                int k = k0 + 2*jj;
                float v0 = fmaf(sc[k],   f.x, sh[k]);   v0 = (v0 > 0.f) ? v0 : 0.2f*v0;
                float v1 = fmaf(sc[k+1], f.y, sh[k+1]); v1 = (v1 > 0.f) ? v1 : 0.2f*v1;
                As2[r*65 + (k >> 1)] = __floats2half2_rn(v0, v1);
            }
        }
    }
    __syncthreads();

    const uint32_t* A32 = (const uint32_t*)(smemraw + C3_AS);
    const uint32_t* W32h = (const uint32_t*)(smemraw + C3_WH);
    const uint32_t* W32l = (const uint32_t*)(smemraw + C3_WL);
    int gid = lane >> 2, tid = lane & 3;
    int nb = w >> 1, mtb = (w & 1)*5;
    float d[5][4];
#pragma unroll
    for (int m = 0; m < 5; m++)
#pragma unroll
        for (int j = 0; j < 4; j++) d[m][j] = 0.f;

#pragma unroll
    for (int k0 = 0; k0 < 8; k0++) {
        int kc = k0*8 + tid;
        uint32_t bh0 = W32h[(nb*8+gid)*65 + kc];
        uint32_t bh1 = W32h[(nb*8+gid)*65 + kc + 4];
        uint32_t bl0 = W32l[(nb*8+gid)*65 + kc];
        uint32_t bl1 = W32l[(nb*8+gid)*65 + kc + 4];
#pragma unroll
        for (int m = 0; m < 5; m++) {
            int row = (mtb + m)*16 + gid;
            uint32_t a0 = A32[row*65 + kc];
            uint32_t a1 = A32[(row+8)*65 + kc];
            uint32_t a2 = A32[row*65 + kc + 4];
            uint32_t a3 = A32[(row+8)*65 + kc + 4];
            mma16816(d[m], a0, a1, a2, a3, bh0, bh1);
            mma16816(d[m], a0, a1, a2, a3, bl0, bl1);
        }
    }

    {
        int col = nb*8 + tid*2;
        float se = 0.f, qe = 0.f, so = 0.f, qo = 0.f;
#pragma unroll
        for (int m = 0; m < 5; m++) {
            int row = (mtb + m)*16 + gid;
            h3s[row*25 + col]       = d[m][0];
            h3s[row*25 + col+1]     = d[m][1];
            h3s[(row+8)*25 + col]   = d[m][2];
            h3s[(row+8)*25 + col+1] = d[m][3];
            se += d[m][0] + d[m][2]; qe += d[m][0]*d[m][0] + d[m][2]*d[m][2];
            so += d[m][1] + d[m][3]; qo += d[m][1]*d[m][1] + d[m][3]*d[m][3];
        }
        atomicAdd(&red[col], se);
        atomicAdd(&red[24 + col], qe);
        atomicAdd(&red[col+1], so);
        atomicAdd(&red[24 + col+1], qo);
    }
    __syncthreads();

    {
        int pl = t / 24, c2 = t % 24;
        float mx = -3.4e38f, mn = 3.4e38f;
#pragma unroll
        for (int kk = 0; kk < KNN; kk++) {
            float v = h3s[(pl*KNN + kk)*25 + c2];
            mx = fmaxf(mx, v); mn = fminf(mn, v);
        }
        int pt = blk*8 + pl;
        g_pmax[pt*24 + c2] = mx;
        g_pmin[pt*24 + c2] = mn;
    }
    if (t < 24) {
        atomicAdd(&g_sum[2*HD + t],   red[t]);
        atomicAdd(&g_sumsq[2*HD + t], red[24 + t]);
    }
    __threadfence();
    __syncthreads();
    if (t == 0) lastflag = (atomicAdd(&g_cnt[2], 1) == (int)gridDim.x - 1);
    __syncthreads();
    if (lastflag) bn_finalize(2, 24, invN, bn3g, bn3b, t);
}

/* ---------------- K6: ResNet-FC head: mma 3-term split (verified) ----------- */
#define H_NET 0
#define H_AH  32768
#define H_AL  49408
#define H_WH  66048
#define H_WL  99328
#define H_CB  132608
#define H_PB  138752
#define H_FO  139520
#define SMEMH 140288
__global__ void __launch_bounds__(256) k_head(const float* __restrict__ p,
                       const float* __restrict__ fpw, const float* __restrict__ fpb,
                       const float* __restrict__ fcw, const float* __restrict__ fcb,
                       const float* __restrict__ b0w, const float* __restrict__ b0b,
                       const float* __restrict__ b1w, const float* __restrict__ b1b,
                       const float* __restrict__ fow, const float* __restrict__ fob,
                       float* __restrict__ out) {
    extern __shared__ char sm[];
    float*   net = (float*)(sm + H_NET);
    __half2* Ah2 = (__half2*)(sm + H_AH);
    __half2* Al2 = (__half2*)(sm + H_AL);
    __half*  WhH = (__half*)(sm + H_WH);
    __half*  WlH = (__half*)(sm + H_WL);
    float*   cb  = (float*)(sm + H_CB);
    float*   pb  = (float*)(sm + H_PB);
    float*   fo  = (float*)(sm + H_FO);

    int t = threadIdx.x, lane = t & 31, w = t >> 5;
    int gid = lane >> 2, tid = lane & 3;
    int mt = w & 3, nh = w >> 2;
    int row = mt*16 + gid;
    int base = blockIdx.x * 64;

    for (int e = t; e < 64*CD; e += 256) {
        int c2 = e % 24;
        float scv = g_scale[2*HD + c2], shv = g_shift[2*HD + c2];
        float v = (scv >= 0.f) ? g_pmax[base*24 + e] : g_pmin[base*24 + e];
        v = fmaf(scv, v, shv);
        cb[e] = (v > 0.f) ? v : 0.2f*v;
    }
    if (t < 192) pb[t] = p[base*3 + t];
    if (t < 128) fo[t] = fow[t];
    __syncthreads();

    int cg  = (t & 31) * 4;
    int row0 = (t >> 5) * 8;

    { /* net = p @ fc_p_w + b */
        float4 w0 = *(const float4*)&fpw[0*HD + cg];
        float4 w1 = *(const float4*)&fpw[1*HD + cg];
        float4 w2 = *(const float4*)&fpw[2*HD + cg];
        float4 b4 = *(const float4*)&fpb[cg];
#pragma unroll
        for (int rr = 0; rr < 8; rr++) {
            int rw = row0 + rr;
            float p0 = pb[rw*3+0], p1 = pb[rw*3+1], p2 = pb[rw*3+2];
            float4 v;
            v.x = fmaf(p0,w0.x, fmaf(p1,w1.x, fmaf(p2,w2.x, b4.x)));
            v.y = fmaf(p0,w0.y, fmaf(p1,w1.y, fmaf(p2,w2.y, b4.y)));
            v.z = fmaf(p0,w0.z, fmaf(p1,w1.z, fmaf(p2,w2.z, b4.z)));
            v.w = fmaf(p0,w0.w, fmaf(p1,w1.w, fmaf(p2,w2.w, b4.w)));
            *(float4*)&net[rw*128 + cg] = v;
        }
    }
    __syncthreads();

    const uint32_t* A32h = (const uint32_t*)(sm + H_AH);
    const uint32_t* A32l = (const uint32_t*)(sm + H_AL);
    const uint32_t* W32h = (const uint32_t*)(sm + H_WH);
    const uint32_t* W32l = (const uint32_t*)(sm + H_WL);

    for (int i = 0; i < NB; i++) {
        { /* net += c @ fc_c[i] + b ; split relu(net) -> Ah/Al */
            float4 b4 = *(const float4*)&fcb[i*HD + cg];
            ull acc2[8][4];
#pragma unroll
            for (int rr = 0; rr < 8; rr++) {
                float4 v = *(const float4*)&net[(row0+rr)*128 + cg];
                acc2[rr][0] = pack2(v.x + b4.x, 0.f);
                acc2[rr][1] = pack2(v.y + b4.y, 0.f);
                acc2[rr][2] = pack2(v.z + b4.z, 0.f);
                acc2[rr][3] = pack2(v.w + b4.w, 0.f);
            }
#pragma unroll 2
            for (int k = 0; k < CD; k += 2) {
                float4 wa = __ldg((const float4*)&fcw[(i*CD + k)*HD + cg]);
                float4 wb = __ldg((const float4*)&fcw[(i*CD + k + 1)*HD + cg]);
                ull wx = pack2(wa.x, wb.x), wy = pack2(wa.y, wb.y);
                ull wz = pack2(wa.z, wb.z), ww = pack2(wa.w, wb.w);
#pragma unroll
                for (int rr = 0; rr < 8; rr++) {
                    ull a = *(const ull*)&cb[(row0+rr)*24 + k];
                    acc2[rr][0] = ffma2(a, wx, acc2[rr][0]);
                    acc2[rr][1] = ffma2(a, wy, acc2[rr][1]);
                    acc2[rr][2] = ffma2(a, wz, acc2[rr][2]);
                    acc2[rr][3] = ffma2(a, ww, acc2[rr][3]);
                }
            }
#pragma unroll
            for (int rr = 0; rr < 8; rr++) {
                int rw = row0 + rr;
                float2 f0 = unpack2(acc2[rr][0]), f1 = unpack2(acc2[rr][1]);
                float2 f2 = unpack2(acc2[rr][2]), f3 = unpack2(acc2[rr][3]);
                float4 v; v.x = f0.x+f0.y; v.y = f1.x+f1.y; v.z = f2.x+f2.y; v.w = f3.x+f3.y;
                *(float4*)&net[rw*128 + cg] = v;
                float ax = fmaxf(v.x,0.f), ay = fmaxf(v.y,0.f);
                float az = fmaxf(v.z,0.f), aw = fmaxf(v.w,0.f);
                __half hx = __float2half(ax), hy = __float2half(ay);
                __half hz = __float2half(az), hw = __float2half(aw);
                Ah2[rw*65 + (cg>>1)]     = __halves2half2(hx, hy);
                Ah2[rw*65 + (cg>>1) + 1] = __halves2half2(hz, hw);
                Al2[rw*65 + (cg>>1)]     = __halves2half2(__float2half(ax - __half2float(hx)),
                                                          __float2half(ay - __half2float(hy)));
                Al2[rw*65 + (cg>>1) + 1] = __halves2half2(__float2half(az - __half2float(hz)),
                                                          __float2half(aw - __half2float(hw)));
            }
        }
        { /* stage W0 hi/lo */
            const float* wb = b0w + (size_t)i*HD*HD;
            for (int e = t; e < HD*HD; e += 256) {
                float vv = wb[e];
                int k = e >> 7, n = e & 127;
                __half hi = __float2half(vv);
                WhH[n*130 + k] = hi;
                WlH[n*130 + k] = __float2half(vv - __half2float(hi));
            }
        }
        __syncthreads();
        /* mma blk0 */
        float d0[8][4];
#pragma unroll
        for (int nb = 0; nb < 8; nb++)
#pragma unroll
            for (int j = 0; j < 4; j++) d0[nb][j] = 0.f;
#pragma unroll
        for (int k0 = 0; k0 < 8; k0++) {
            int kc = k0*8 + tid;
            uint32_t ah0 = A32h[row*65 + kc],     ah1 = A32h[(row+8)*65 + kc];
            uint32_t ah2 = A32h[row*65 + kc + 4], ah3 = A32h[(row+8)*65 + kc + 4];
            uint32_t al0 = A32l[row*65 + kc],     al1 = A32l[(row+8)*65 + kc];
            uint32_t al2 = A32l[row*65 + kc + 4], al3 = A32l[(row+8)*65 + kc + 4];
#pragma unroll
            for (int nb = 0; nb < 8; nb++) {
                int nr = nh*64 + nb*8 + gid;
                uint32_t bh0 = W32h[nr*65 + kc], bh1 = W32h[nr*65 + kc + 4];
                uint32_t bl0 = W32l[nr*65 + kc], bl1 = W32l[nr*65 + kc + 4];
                mma16816(d0[nb], ah0, ah1, ah2, ah3, bh0, bh1);
                mma16816(d0[nb], ah0, ah1, ah2, ah3, bl0, bl1);
                mma16816(d0[nb], al0, al1, al2, al3, bh0, bh1);
            }
        }
        __syncthreads();
        /* epi0: hh = relu(d0+b0b) -> Ah/Al ; stage W1 */
#pragma unroll
        for (int nb = 0; nb < 8; nb++) {
            int col = nh*64 + nb*8 + tid*2;
            float bb0 = __ldg(&b0b[i*HD + col]);
            float bb1 = __ldg(&b0b[i*HD + col + 1]);
            float v0 = fmaxf(d0[nb][0] + bb0, 0.f);
            float v1 = fmaxf(d0[nb][1] + bb1, 0.f);
            float v2 = fmaxf(d0[nb][2] + bb0, 0.f);
            float v3 = fmaxf(d0[nb][3] + bb1, 0.f);
            __half h0 = __float2half(v0), h1 = __float2half(v1);
            __half h2 = __float2half(v2), h3 = __float2half(v3);
            Ah2[row*65 + (col>>1)]     = __halves2half2(h0, h1);
            Ah2[(row+8)*65 + (col>>1)] = __halves2half2(h2, h3);
            Al2[row*65 + (col>>1)]     = __halves2half2(__float2half(v0 - __half2float(h0)),
                                                        __float2half(v1 - __half2float(h1)));
            Al2[(row+8)*65 + (col>>1)] = __halves2half2(__float2half(v2 - __half2float(h2)),
                                                        __float2half(v3 - __half2float(h3)));
        }
        {
            const float* wb = b1w + (size_t)i*HD*HD;
            for (int e = t; e < HD*HD; e += 256) {
                float vv = wb[e];
                int k = e >> 7, n = e & 127;
                __half hi = __float2half(vv);
                WhH[n*130 + k] = hi;
                WlH[n*130 + k] = __float2half(vv - __half2float(hi));
            }
        }
        __syncthreads();
        /* mma blk1 */
        float d1[8][4];
#pragma unroll
        for (int nb = 0; nb < 8; nb++)
#pragma unroll
            for (int j = 0; j < 4; j++) d1[nb][j] = 0.f;
#pragma unroll
        for (int k0 = 0; k0 < 8; k0++) {
            int kc = k0*8 + tid;
            uint32_t ah0 = A32h[row*65 + kc],     ah1 = A32h[(row+8)*65 + kc];
            uint32_t ah2 = A32h[row*65 + kc + 4], ah3 = A32h[(row+8)*65 + kc + 4];
            uint32_t al0 = A32l[row*65 + kc],     al1 = A32l[(row+8)*65 + kc];
            uint32_t al2 = A32l[row*65 + kc + 4], al3 = A32l[(row+8)*65 + kc + 4];
#pragma unroll
            for (int nb = 0; nb < 8; nb++) {
                int nr = nh*64 + nb*8 + gid;
                uint32_t bh0 = W32h[nr*65 + kc], bh1 = W32h[nr*65 + kc + 4];
                uint32_t bl0 = W32l[nr*65 + kc], bl1 = W32l[nr*65 + kc + 4];
                mma16816(d1[nb], ah0, ah1, ah2, ah3, bh0, bh1);
                mma16816(d1[nb], ah0, ah1, ah2, ah3, bl0, bl1);
                mma16816(d1[nb], al0, al1, al2, al3, bh0, bh1);
            }
        }
        /* epi1: net += d1 + b1b */
#pragma unroll
        for (int nb = 0; nb < 8; nb++) {
            int col = nh*64 + nb*8 + tid*2;
            float bb0 = __ldg(&b1b[i*HD + col]);
            float bb1 = __ldg(&b1b[i*HD + col + 1]);
            net[row*128 + col]         += d1[nb][0] + bb0;
            net[row*128 + col + 1]     += d1[nb][1] + bb1;
            net[(row+8)*128 + col]     += d1[nb][2] + bb0;
            net[(row+8)*128 + col + 1] += d1[nb][3] + bb1;
        }
        __syncthreads();
    }

    if (t < 64) {
        float s = fob[0];
        for (int c2 = 0; c2 < HD; c2++)
            s = fmaf(fmaxf(net[t*128 + c2], 0.f), fo[c2], s);
        out[base + t] = s;
    }
}

/* ---------------- launch ---------------- */
extern "C" void kernel_launch(void* const* d_in, const int* in_sizes, int n_in,
                              void* d_out, int out_size) {
    (void)in_sizes; (void)n_in; (void)out_size;
    const float* p     = (const float*)d_in[0];
    const float* pc    = (const float*)d_in[1];
    const float* feat  = (const float*)d_in[2];
    const float* w1    = (const float*)d_in[3];
    const float* bn1g  = (const float*)d_in[4];
    const float* bn1b  = (const float*)d_in[5];
    const float* w2    = (const float*)d_in[6];
    const float* bn2g  = (const float*)d_in[7];
    const float* bn2b  = (const float*)d_in[8];
    const float* w3    = (const float*)d_in[9];
    const float* bn3g  = (const float*)d_in[10];
    const float* bn3b  = (const float*)d_in[11];
    const float* fpw   = (const float*)d_in[12];
    const float* fpb   = (const float*)d_in[13];
    const float* fcw   = (const float*)d_in[14];
    const float* fcb   = (const float*)d_in[15];
    const float* b0w   = (const float*)d_in[16];
    const float* b0b   = (const float*)d_in[17];
    const float* b1w   = (const float*)d_in[18];
    const float* b1b   = (const float*)d_in[19];
    const float* fow   = (const float*)d_in[20];
    const float* fob   = (const float*)d_in[21];
    float* out = (float*)d_out;

    cudaFuncSetAttribute(k_conv2,  cudaFuncAttributeMaxDynamicSharedMemorySize, C2_SMEM);
    cudaFuncSetAttribute(k_conv3p, cudaFuncAttributeMaxDynamicSharedMemorySize, SMEM3);
    cudaFuncSetAttribute(k_head,   cudaFuncAttributeMaxDynamicSharedMemorySize, SMEMH);

    float invN = 1.0f / (float)NROWS;

    k_preU<<<(BSZ*NY)/32, 128>>>(pc, feat, w1);
    k_preV<<<NPTS/64, 128>>>(p, w1);
    k_preW<<<HD*HD/128, 128>>>(w2);
    k_knn<<<dim3(NX/128, BSZ), 256>>>(p, pc);
    k_stats1<<<NROWS/512, 256>>>(bn1g, bn1b, invN);
    k_conv2<<<NROWS/128, 256, C2_SMEM>>>(bn2g, bn2b, invN);
    k_conv3p<<<NROWS/160, 192, SMEM3>>>(w3, bn3g, bn3b, invN);
    k_head<<<NPTS/64, 256, SMEMH>>>(p, fpw, fpb, fcw, fcb,
                                    b0w, b0b, b1w, b1b, fow, fob, out);
}